// round 1
// baseline (speedup 1.0000x reference)
#include <cuda_runtime.h>
#include <cuda_fp16.h>

#define BB   2
#define KK   512
#define QQ   512
#define TT   128
#define NREP 8

// ---------------- device scratch (no allocation allowed) ----------------
__device__ float g_k[BB * KK * TT];
__device__ float g_q[BB * QQ * TT];
__device__ float g_v[BB * KK * TT];
__device__ float g_accr[NREP * BB * QQ * TT];   // replicated k-sum accumulator
__device__ float g_acc[BB * QQ * TT];           // collapsed accumulator

// ---------------- zero the replicated accumulator ----------------
__global__ void zero_kernel() {
    int i = blockIdx.x * blockDim.x + threadIdx.x;
    if (i < NREP * BB * QQ * TT) g_accr[i] = 0.0f;
}

// ---------------- generic out[r,u] = sum_t in[r,t] * W[u,t] ----------------
// rows multiple of 64. 256 threads, 64x128 output tile per CTA, 4x8 micro-tile.
__global__ __launch_bounds__(256) void gemm_nt(const float* __restrict__ in,
                                               const float* __restrict__ W,
                                               float* __restrict__ out) {
    extern __shared__ float sm[];
    float* sW  = sm;                 // [128][129]
    float* sin = sm + 128 * 129;     // [64][129]

    int tid = threadIdx.x;
    int tx = tid & 15;               // -> u = tx + 16*j
    int ty = tid >> 4;               // -> r = r0 + ty*4 + i
    int r0 = blockIdx.x * 64;

    for (int i = tid; i < 128 * 128; i += 256) {
        int u = i >> 7, t = i & 127;
        sW[u * 129 + t] = W[i];
    }
    for (int i = tid; i < 64 * 128; i += 256) {
        int r = i >> 7, t = i & 127;
        sin[r * 129 + t] = in[(size_t)r0 * 128 + i];
    }
    __syncthreads();

    float acc[4][8];
#pragma unroll
    for (int i = 0; i < 4; i++)
#pragma unroll
        for (int j = 0; j < 8; j++) acc[i][j] = 0.0f;

#pragma unroll 4
    for (int t = 0; t < 128; t++) {
        float a[4], b[8];
#pragma unroll
        for (int i = 0; i < 4; i++) a[i] = sin[(ty * 4 + i) * 129 + t];
#pragma unroll
        for (int j = 0; j < 8; j++) b[j] = sW[(tx + 16 * j) * 129 + t];
#pragma unroll
        for (int i = 0; i < 4; i++)
#pragma unroll
            for (int j = 0; j < 8; j++) acc[i][j] = fmaf(a[i], b[j], acc[i][j]);
    }

#pragma unroll
    for (int i = 0; i < 4; i++)
#pragma unroll
        for (int j = 0; j < 8; j++)
            out[(size_t)(r0 + ty * 4 + i) * 128 + tx + 16 * j] = acc[i][j];
}

// ---------------- main: one CTA per (b,k) ----------------
// L[q,u] = sum_t q[b,q,t] * (Wl[u,t]*k[b,k,t]); swishmax over q; scaled-v REDG.
__global__ __launch_bounds__(256) void attn_kernel(const float* __restrict__ Wl) {
    extern __shared__ char smraw[];
    float* wk   = (float*)smraw;                    // [128][129] fp32  (Wl ⊙ k_row)
    __half* Ls  = (__half*)(wk + 128 * 129);        // [512][128] fp16 logits
    float* qt   = (float*)(Ls + 512 * 128);         // [64][128] fp32 q tile
    float* mred = qt + 64 * 128;                    // [2][128]
    float* sred = mred + 256;                       // [2][128]

    int tid = threadIdx.x;
    int b  = blockIdx.x >> 9;
    int kk = blockIdx.x & 511;

    const float* krow = g_k + ((size_t)b * KK + kk) * TT;
    for (int i = tid; i < 128 * 128; i += 256) {
        int u = i >> 7, t = i & 127;
        wk[u * 129 + t] = Wl[i] * krow[t];
    }
    __syncthreads();

    int tx = tid & 15;   // u = tx + 16*j
    int ty = tid >> 4;   // q = qc*64 + ty*4 + i

    // ---- GEMM: fill Ls ----
    for (int qc = 0; qc < 8; qc++) {
        const float* qsrc = g_q + ((size_t)b * QQ + qc * 64) * TT;
        for (int i = tid; i < 64 * 128; i += 256) qt[i] = qsrc[i];
        __syncthreads();

        float acc[4][8];
#pragma unroll
        for (int i = 0; i < 4; i++)
#pragma unroll
            for (int j = 0; j < 8; j++) acc[i][j] = 0.0f;

#pragma unroll 4
        for (int t = 0; t < 128; t++) {
            float a[4], bb[8];
#pragma unroll
            for (int i = 0; i < 4; i++) a[i] = qt[(ty * 4 + i) * 128 + t];
#pragma unroll
            for (int j = 0; j < 8; j++) bb[j] = wk[(tx + 16 * j) * 129 + t];
#pragma unroll
            for (int i = 0; i < 4; i++)
#pragma unroll
                for (int j = 0; j < 8; j++) acc[i][j] = fmaf(a[i], bb[j], acc[i][j]);
        }
#pragma unroll
        for (int i = 0; i < 4; i++)
#pragma unroll
            for (int j = 0; j < 8; j++)
                Ls[(qc * 64 + ty * 4 + i) * 128 + tx + 16 * j] = __float2half(acc[i][j]);
        __syncthreads();
    }

    // ---- swishmax over q, per column u (2 threads per column) ----
    int u = tid & 127;
    int h = tid >> 7;
    int q0 = h * 256;

    float mx = -1e30f;
#pragma unroll 4
    for (int q = q0; q < q0 + 256; q++)
        mx = fmaxf(mx, __half2float(Ls[q * 128 + u]));
    mred[h * 128 + u] = mx;
    __syncthreads();
    float m = fmaxf(mred[u], mred[128 + u]);

    float ss = 0.0f;
#pragma unroll 4
    for (int q = q0; q < q0 + 256; q++) {
        float x  = __half2float(Ls[q * 128 + u]);
        float xe = x * __expf(x - m);
        Ls[q * 128 + u] = __float2half(xe);   // overwrite with x*exp(x-m)
        ss += fabsf(xe);
    }
    sred[h * 128 + u] = ss;
    __syncthreads();
    float inv = 1.0f / (sred[u] + sred[128 + u] + 1.0f);

    // ---- apply v and accumulate over k (replicated atomics) ----
    float vu = g_v[((size_t)b * KK + kk) * TT + u] * inv;
    float* dst = g_accr + (((size_t)(kk & (NREP - 1)) * BB + b) * QQ) * TT;
#pragma unroll 4
    for (int q = q0; q < q0 + 256; q++) {
        float val = vu * __half2float(Ls[q * 128 + u]);
        atomicAdd(&dst[q * TT + u], val);
    }
}

// ---------------- collapse replicas ----------------
__global__ void collapse_kernel() {
    int i = blockIdx.x * blockDim.x + threadIdx.x;
    if (i < BB * QQ * TT) {
        float s = 0.0f;
#pragma unroll
        for (int r = 0; r < NREP; r++) s += g_accr[(size_t)r * BB * QQ * TT + i];
        g_acc[i] = s;
    }
}

// ---------------- launch ----------------
extern "C" void kernel_launch(void* const* d_in, const int* in_sizes, int n_in,
                              void* d_out, int out_size) {
    const float* q_in = (const float*)d_in[0];
    const float* k_in = (const float*)d_in[1];
    const float* v_in = (const float*)d_in[2];
    const float* Wk   = (const float*)d_in[3];
    const float* Wq   = (const float*)d_in[4];
    const float* Wv   = (const float*)d_in[5];
    const float* Wl   = (const float*)d_in[6];
    const float* Wo   = (const float*)d_in[7];
    float* out = (float*)d_out;

    const int SMEM_GEMM = (128 * 129 + 64 * 129) * 4;                    // 99072
    const int SMEM_ATTN = 128 * 129 * 4 + 512 * 128 * 2 + 64 * 128 * 4
                        + 2 * 128 * 4 + 2 * 128 * 4;                     // 231936

    cudaFuncSetAttribute(gemm_nt, cudaFuncAttributeMaxDynamicSharedMemorySize, SMEM_GEMM);
    cudaFuncSetAttribute(attn_kernel, cudaFuncAttributeMaxDynamicSharedMemorySize, SMEM_ATTN);

    float *pk, *pq, *pv, *pacc;
    cudaGetSymbolAddress((void**)&pk,  g_k);
    cudaGetSymbolAddress((void**)&pq,  g_q);
    cudaGetSymbolAddress((void**)&pv,  g_v);
    cudaGetSymbolAddress((void**)&pacc, g_acc);

    zero_kernel<<<(NREP * BB * QQ * TT + 255) / 256, 256>>>();

    // projections: rows = B*512 = 1024 -> 16 CTAs each
    gemm_nt<<<16, 256, SMEM_GEMM>>>(q_in, Wq, pq);
    gemm_nt<<<16, 256, SMEM_GEMM>>>(k_in, Wk, pk);
    gemm_nt<<<16, 256, SMEM_GEMM>>>(v_in, Wv, pv);

    attn_kernel<<<BB * KK, 256, SMEM_ATTN>>>(Wl);

    collapse_kernel<<<(BB * QQ * TT + 255) / 256, 256>>>();

    gemm_nt<<<16, 256, SMEM_GEMM>>>(pacc, Wo, out);
}

// round 2
// speedup vs baseline: 1.0030x; 1.0030x over previous
#include <cuda_runtime.h>
#include <cuda_fp16.h>

#define BB   2
#define KK   512
#define QQ   512
#define TT   128
#define NREP 8

// ---------------- device scratch (no allocation allowed) ----------------
__device__ float g_k[BB * KK * TT];
__device__ float g_q[BB * QQ * TT];
__device__ float g_v[BB * KK * TT];
__device__ float g_accr[NREP * BB * QQ * TT];   // replicated k-sum accumulator
__device__ float g_acc[BB * QQ * TT];           // collapsed accumulator

// ---------------- zero the replicated accumulator ----------------
__global__ void zero_kernel() {
    int i = blockIdx.x * blockDim.x + threadIdx.x;
    if (i < NREP * BB * QQ * TT) g_accr[i] = 0.0f;
}

// ---------------- generic out[r,u] = sum_t in[r,t] * W[u,t] ----------------
// rows multiple of 64. 256 threads, 64x128 output tile per CTA, 4x8 micro-tile.
__global__ __launch_bounds__(256) void gemm_nt(const float* __restrict__ in,
                                               const float* __restrict__ W,
                                               float* __restrict__ out) {
    extern __shared__ float sm[];
    float* sW  = sm;                 // [128][129]
    float* sin = sm + 128 * 129;     // [64][129]

    int tid = threadIdx.x;
    int tx = tid & 15;               // -> u = tx + 16*j
    int ty = tid >> 4;               // -> r = r0 + ty*4 + i
    int r0 = blockIdx.x * 64;

    for (int i = tid; i < 128 * 128; i += 256) {
        int u = i >> 7, t = i & 127;
        sW[u * 129 + t] = W[i];
    }
    for (int i = tid; i < 64 * 128; i += 256) {
        int r = i >> 7, t = i & 127;
        sin[r * 129 + t] = in[(size_t)r0 * 128 + i];
    }
    __syncthreads();

    float acc[4][8];
#pragma unroll
    for (int i = 0; i < 4; i++)
#pragma unroll
        for (int j = 0; j < 8; j++) acc[i][j] = 0.0f;

#pragma unroll 4
    for (int t = 0; t < 128; t++) {
        float a[4], b[8];
#pragma unroll
        for (int i = 0; i < 4; i++) a[i] = sin[(ty * 4 + i) * 129 + t];
#pragma unroll
        for (int j = 0; j < 8; j++) b[j] = sW[(tx + 16 * j) * 129 + t];
#pragma unroll
        for (int i = 0; i < 4; i++)
#pragma unroll
            for (int j = 0; j < 8; j++) acc[i][j] = fmaf(a[i], b[j], acc[i][j]);
    }

#pragma unroll
    for (int i = 0; i < 4; i++)
#pragma unroll
        for (int j = 0; j < 8; j++)
            out[(size_t)(r0 + ty * 4 + i) * 128 + tx + 16 * j] = acc[i][j];
}

// ---------------- main: one CTA per (b,k) ----------------
// L[q,u] = sum_t q[b,q,t] * (Wl[u,t]*k[b,k,t]); swishmax over q; scaled-v REDG.
__global__ __launch_bounds__(256) void attn_kernel(const float* __restrict__ Wl) {
    extern __shared__ char smraw[];
    float* wk   = (float*)smraw;                    // [128][129] fp32  (Wl ⊙ k_row)
    __half* Ls  = (__half*)(wk + 128 * 129);        // [512][128] fp16 logits
    float* qt   = (float*)(Ls + 512 * 128);         // [64][128] fp32 q tile
    float* mred = qt + 64 * 128;                    // [2][128]
    float* sred = mred + 256;                       // [2][128]

    int tid = threadIdx.x;
    int b  = blockIdx.x >> 9;
    int kk = blockIdx.x & 511;

    const float* krow = g_k + ((size_t)b * KK + kk) * TT;
    for (int i = tid; i < 128 * 128; i += 256) {
        int u = i >> 7, t = i & 127;
        wk[u * 129 + t] = Wl[i] * krow[t];
    }
    __syncthreads();

    int tx = tid & 15;   // u = tx + 16*j
    int ty = tid >> 4;   // q = qc*64 + ty*4 + i

    // ---- GEMM: fill Ls ----
    for (int qc = 0; qc < 8; qc++) {
        const float* qsrc = g_q + ((size_t)b * QQ + qc * 64) * TT;
        for (int i = tid; i < 64 * 128; i += 256) qt[i] = qsrc[i];
        __syncthreads();

        float acc[4][8];
#pragma unroll
        for (int i = 0; i < 4; i++)
#pragma unroll
            for (int j = 0; j < 8; j++) acc[i][j] = 0.0f;

#pragma unroll 4
        for (int t = 0; t < 128; t++) {
            float a[4], bb[8];
#pragma unroll
            for (int i = 0; i < 4; i++) a[i] = qt[(ty * 4 + i) * 128 + t];
#pragma unroll
            for (int j = 0; j < 8; j++) bb[j] = wk[(tx + 16 * j) * 129 + t];
#pragma unroll
            for (int i = 0; i < 4; i++)
#pragma unroll
                for (int j = 0; j < 8; j++) acc[i][j] = fmaf(a[i], bb[j], acc[i][j]);
        }
#pragma unroll
        for (int i = 0; i < 4; i++)
#pragma unroll
            for (int j = 0; j < 8; j++)
                Ls[(qc * 64 + ty * 4 + i) * 128 + tx + 16 * j] = __float2half(acc[i][j]);
        __syncthreads();
    }

    // ---- swishmax over q, per column u (2 threads per column) ----
    int u = tid & 127;
    int h = tid >> 7;
    int q0 = h * 256;

    float mx = -1e30f;
#pragma unroll 4
    for (int q = q0; q < q0 + 256; q++)
        mx = fmaxf(mx, __half2float(Ls[q * 128 + u]));
    mred[h * 128 + u] = mx;
    __syncthreads();
    float m = fmaxf(mred[u], mred[128 + u]);

    float ss = 0.0f;
#pragma unroll 4
    for (int q = q0; q < q0 + 256; q++) {
        float x  = __half2float(Ls[q * 128 + u]);
        float xe = x * __expf(x - m);
        Ls[q * 128 + u] = __float2half(xe);   // overwrite with x*exp(x-m)
        ss += fabsf(xe);
    }
    sred[h * 128 + u] = ss;
    __syncthreads();
    float inv = 1.0f / (sred[u] + sred[128 + u] + 1.0f);

    // ---- apply v and accumulate over k (replicated atomics) ----
    float vu = g_v[((size_t)b * KK + kk) * TT + u] * inv;
    float* dst = g_accr + (((size_t)(kk & (NREP - 1)) * BB + b) * QQ) * TT;
#pragma unroll 4
    for (int q = q0; q < q0 + 256; q++) {
        float val = vu * __half2float(Ls[q * 128 + u]);
        atomicAdd(&dst[q * TT + u], val);
    }
}

// ---------------- collapse replicas ----------------
__global__ void collapse_kernel() {
    int i = blockIdx.x * blockDim.x + threadIdx.x;
    if (i < BB * QQ * TT) {
        float s = 0.0f;
#pragma unroll
        for (int r = 0; r < NREP; r++) s += g_accr[(size_t)r * BB * QQ * TT + i];
        g_acc[i] = s;
    }
}

// ---------------- launch ----------------
extern "C" void kernel_launch(void* const* d_in, const int* in_sizes, int n_in,
                              void* d_out, int out_size) {
    const float* q_in = (const float*)d_in[0];
    const float* k_in = (const float*)d_in[1];
    const float* v_in = (const float*)d_in[2];
    const float* Wk   = (const float*)d_in[3];
    const float* Wq   = (const float*)d_in[4];
    const float* Wv   = (const float*)d_in[5];
    const float* Wl   = (const float*)d_in[6];
    const float* Wo   = (const float*)d_in[7];
    float* out = (float*)d_out;

    const int SMEM_GEMM = (128 * 129 + 64 * 129) * 4;                    // 99072
    const int SMEM_ATTN = 128 * 129 * 4 + 512 * 128 * 2 + 64 * 128 * 4
                        + 2 * 128 * 4 + 2 * 128 * 4;                     // 231936

    cudaFuncSetAttribute(gemm_nt, cudaFuncAttributeMaxDynamicSharedMemorySize, SMEM_GEMM);
    cudaFuncSetAttribute(attn_kernel, cudaFuncAttributeMaxDynamicSharedMemorySize, SMEM_ATTN);

    float *pk, *pq, *pv, *pacc;
    cudaGetSymbolAddress((void**)&pk,  g_k);
    cudaGetSymbolAddress((void**)&pq,  g_q);
    cudaGetSymbolAddress((void**)&pv,  g_v);
    cudaGetSymbolAddress((void**)&pacc, g_acc);

    zero_kernel<<<(NREP * BB * QQ * TT + 255) / 256, 256>>>();

    // projections: rows = B*512 = 1024 -> 16 CTAs each
    gemm_nt<<<16, 256, SMEM_GEMM>>>(q_in, Wq, pq);
    gemm_nt<<<16, 256, SMEM_GEMM>>>(k_in, Wk, pk);
    gemm_nt<<<16, 256, SMEM_GEMM>>>(v_in, Wv, pv);

    attn_kernel<<<BB * KK, 256, SMEM_ATTN>>>(Wl);

    collapse_kernel<<<(BB * QQ * TT + 255) / 256, 256>>>();

    gemm_nt<<<16, 256, SMEM_GEMM>>>(pacc, Wo, out);
}

// round 4
// speedup vs baseline: 2.0805x; 2.0744x over previous
#include <cuda_runtime.h>
#include <cuda_fp16.h>
#include <cstdint>

#define BB 2
#define KK 512
#define QQ 512
#define TT 128

// ---------------- device scratch ----------------
__device__ float g_k[BB * KK * TT];
__device__ float g_q[BB * QQ * TT];
__device__ float g_v[BB * KK * TT];
__device__ float g_w[BB * KK * TT];                  // per (b,k,u) scale v_u/(T+e^m)
__device__ float g_acc[BB * QQ * TT];
__device__ __half g_xe[(size_t)BB * KK * TT * QQ];   // 128MB unscaled y = x*e^x
__device__ unsigned char g_wlhi[32768];              // swizzled fp16 Wl hi image
__device__ unsigned char g_wllo[32768];              // swizzled fp16 Wl lo image

// ---------------- helpers ----------------
__device__ __forceinline__ uint32_t smem_u32(const void* p) {
    uint32_t a;
    asm("{ .reg .u64 t; cvta.to.shared.u64 t, %1; cvt.u32.u64 %0, t; }" : "=r"(a) : "l"(p));
    return a;
}
__device__ __forceinline__ void ldsm_x4(uint32_t& r0, uint32_t& r1, uint32_t& r2, uint32_t& r3,
                                        uint32_t addr) {
    asm volatile("ldmatrix.sync.aligned.m8n8.x4.shared.b16 {%0,%1,%2,%3}, [%4];"
                 : "=r"(r0), "=r"(r1), "=r"(r2), "=r"(r3) : "r"(addr));
}
__device__ __forceinline__ void ldsm_x2(uint32_t& r0, uint32_t& r1, uint32_t addr) {
    asm volatile("ldmatrix.sync.aligned.m8n8.x2.shared.b16 {%0,%1}, [%2];"
                 : "=r"(r0), "=r"(r1) : "r"(addr));
}
__device__ __forceinline__ void mma16816(float& d0, float& d1, float& d2, float& d3,
                                         uint32_t a0, uint32_t a1, uint32_t a2, uint32_t a3,
                                         uint32_t b0, uint32_t b1) {
    asm volatile("mma.sync.aligned.m16n8k16.row.col.f32.f16.f16.f32 "
                 "{%0,%1,%2,%3}, {%4,%5,%6,%7}, {%8,%9}, {%0,%1,%2,%3};"
                 : "+f"(d0), "+f"(d1), "+f"(d2), "+f"(d3)
                 : "r"(a0), "r"(a1), "r"(a2), "r"(a3), "r"(b0), "r"(b1));
}

// smem byte layout for pass1 (total exactly 232448)
#define A_HI_OFF 0
#define A_LO_OFF 32768
#define X_OFF    65536
#define L_OFF    98304
#define L_STRIDE 516                      // halves per u row
#define SCR_OFF  (L_OFF + 128 * L_STRIDE * 2)   // 230400: kraw (early) / m2,T2 (late)
#define P1_SMEM  232448

// ---------------- prep: Wl -> hi/lo fp16, swizzled smem image ----------------
// smem A layout: row u = 256B; chunk c (8 halves, 16B) placed at c ^ (u&7)
__global__ void prep_wl(const float* __restrict__ Wl) {
    int i = blockIdx.x * 256 + threadIdx.x;
    if (i >= TT * TT) return;
    int u = i >> 7, t = i & 127;
    float w = Wl[i];
    __half hi = __float2half_rn(w);
    __half lo = __float2half_rn(w - __half2float(hi));
    uint32_t byte = (uint32_t)u * 256u + ((((uint32_t)t >> 3) ^ (u & 7)) << 4) + (t & 7) * 2u;
    *(__half*)(g_wlhi + byte) = hi;
    *(__half*)(g_wllo + byte) = lo;
}

// ---------------- fp32 GEMM 32-row tiles: out[r,u] = sum_t in[r,t]*W[u,t] ----------------
__device__ __forceinline__ void gemm32_body(const float* __restrict__ in,
                                            const float* __restrict__ W,
                                            float* __restrict__ out, int r0) {
    extern __shared__ float smf[];
    float* sW = smf;                 // [128][132]
    float* sI = smf + 128 * 132;     // [32][132]
    int tid = threadIdx.x;
    for (int i = tid; i < 128 * 128; i += 256) { int u = i >> 7, t = i & 127; sW[u * 132 + t] = W[i]; }
    for (int i = tid; i < 32 * 128;  i += 256) { int r = i >> 7, t = i & 127; sI[r * 132 + t] = in[(size_t)r0 * 128 + i]; }
    __syncthreads();
    int tx = tid & 15, ty = tid >> 4;
    float acc[2][8];
#pragma unroll
    for (int i = 0; i < 2; i++)
#pragma unroll
        for (int j = 0; j < 8; j++) acc[i][j] = 0.0f;
    for (int t = 0; t < 128; t += 4) {
        float4 a0 = *(const float4*)&sI[(ty * 2 + 0) * 132 + t];
        float4 a1 = *(const float4*)&sI[(ty * 2 + 1) * 132 + t];
#pragma unroll
        for (int j = 0; j < 8; j++) {
            float4 bv = *(const float4*)&sW[(tx + 16 * j) * 132 + t];
            acc[0][j] = fmaf(a0.x, bv.x, acc[0][j]); acc[0][j] = fmaf(a0.y, bv.y, acc[0][j]);
            acc[0][j] = fmaf(a0.z, bv.z, acc[0][j]); acc[0][j] = fmaf(a0.w, bv.w, acc[0][j]);
            acc[1][j] = fmaf(a1.x, bv.x, acc[1][j]); acc[1][j] = fmaf(a1.y, bv.y, acc[1][j]);
            acc[1][j] = fmaf(a1.z, bv.z, acc[1][j]); acc[1][j] = fmaf(a1.w, bv.w, acc[1][j]);
        }
    }
#pragma unroll
    for (int i = 0; i < 2; i++)
#pragma unroll
        for (int j = 0; j < 8; j++)
            out[(size_t)(r0 + ty * 2 + i) * 128 + tx + 16 * j] = acc[i][j];
}

__global__ __launch_bounds__(256) void gemm32(const float* __restrict__ in,
                                              const float* __restrict__ W,
                                              float* __restrict__ out) {
    gemm32_body(in, W, out, blockIdx.x * 32);
}

__global__ __launch_bounds__(256) void proj3(const float* __restrict__ qi, const float* __restrict__ Wq,
                                             const float* __restrict__ ki, const float* __restrict__ Wk,
                                             const float* __restrict__ vi, const float* __restrict__ Wv) {
    int r0 = blockIdx.x * 32;
    if (blockIdx.y == 0)      gemm32_body(qi, Wq, g_q, r0);
    else if (blockIdx.y == 1) gemm32_body(ki, Wk, g_k, r0);
    else                      gemm32_body(vi, Wv, g_v, r0);
}

// ---------------- pass 1: CTA per (b,k) ----------------
__global__ __launch_bounds__(256) void pass1() {
    extern __shared__ unsigned char sm[];
    int tid = threadIdx.x, wid = tid >> 5, lane = tid & 31;
    int b = blockIdx.x >> 9, kidx = blockIdx.x & 511;

    // A tiles (pre-swizzled) -> smem
    {
        uint4* ah = (uint4*)(sm + A_HI_OFF);
        uint4* al = (uint4*)(sm + A_LO_OFF);
        const uint4* shp = (const uint4*)g_wlhi;
        const uint4* slp = (const uint4*)g_wllo;
        for (int i = tid; i < 2048; i += 256) { ah[i] = shp[i]; al[i] = slp[i]; }
    }
    // k row -> smem scratch
    float* kraw = (float*)(sm + SCR_OFF);
    if (tid < 32)
        ((float4*)kraw)[tid] = ((const float4*)(g_k + ((size_t)b * KK + kidx) * TT))[tid];
    __syncthreads();

    // A fragments: warp wid owns u rows [wid*16, wid*16+16), all K=128 (8 k-steps)
    uint32_t ahi[8][4], alo[8][4];
    {
        int u0 = wid * 16;
        int row = u0 + (lane & 7) + ((lane >> 3) & 1) * 8;
        int cpar = (lane >> 4) & 1;
        int r7 = lane & 7;
        uint32_t rbh = smem_u32(sm + A_HI_OFF) + row * 256;
        uint32_t rbl = smem_u32(sm + A_LO_OFF) + row * 256;
#pragma unroll
        for (int s = 0; s < 8; s++) {
            int chunk = 2 * s + cpar;
            uint32_t off = (uint32_t)((chunk ^ r7) << 4);
            ldsm_x4(ahi[s][0], ahi[s][1], ahi[s][2], ahi[s][3], rbh + off);
            ldsm_x4(alo[s][0], alo[s][1], alo[s][2], alo[s][3], rbl + off);
        }
    }

    uint32_t xbase = smem_u32(sm + X_OFF);
    __half* Lh = (__half*)(sm + L_OFF);

    for (int qt = 0; qt < 4; qt++) {
        // build X[q][t] = fp16(q * k), swizzled chunks; thread -> (q = tid>>1, half h)
        {
            int q = tid >> 1, h = tid & 1;
            const float4* qrow = (const float4*)(g_q + ((size_t)b * QQ + qt * 128 + q) * TT + h * 64);
            const float4* krow = (const float4*)(kraw + h * 64);
            unsigned char* xrow = sm + X_OFF + q * 256;
            int q7 = q & 7;
#pragma unroll
            for (int c8 = 0; c8 < 8; c8++) {
                float4 qa = qrow[c8 * 2], qb = qrow[c8 * 2 + 1];
                float4 ka = krow[c8 * 2], kb = krow[c8 * 2 + 1];
                __half2 h0 = __floats2half2_rn(qa.x * ka.x, qa.y * ka.y);
                __half2 h1 = __floats2half2_rn(qa.z * ka.z, qa.w * ka.w);
                __half2 h2 = __floats2half2_rn(qb.x * kb.x, qb.y * kb.y);
                __half2 h3 = __floats2half2_rn(qb.z * kb.z, qb.w * kb.w);
                int chunk = h * 8 + c8;
                uint4 pk;
                pk.x = *(uint32_t*)&h0; pk.y = *(uint32_t*)&h1;
                pk.z = *(uint32_t*)&h2; pk.w = *(uint32_t*)&h3;
                *(uint4*)(xrow + ((chunk ^ q7) << 4)) = pk;
            }
        }
        __syncthreads();

        // MMA: warp computes u-rows [wid*16, +16) x q-tile [qt*128, +128)
        {
            int u0 = wid * 16;
            int brow7 = lane & 7;
            int bpar = (lane >> 3) & 1;
#pragma unroll 1
            for (int nt = 0; nt < 16; nt++) {
                int q0 = nt * 8;
                int row = q0 + brow7;
                uint32_t rb = xbase + row * 256;
                int r7 = row & 7;
                uint32_t bf[8][2];
#pragma unroll
                for (int s = 0; s < 8; s++) {
                    int chunk = 2 * s + bpar;
                    ldsm_x2(bf[s][0], bf[s][1], rb + ((chunk ^ r7) << 4));
                }
                float d0 = 0, d1 = 0, d2 = 0, d3 = 0;
#pragma unroll
                for (int s = 0; s < 8; s++) {
                    mma16816(d0, d1, d2, d3, ahi[s][0], ahi[s][1], ahi[s][2], ahi[s][3], bf[s][0], bf[s][1]);
                    mma16816(d0, d1, d2, d3, alo[s][0], alo[s][1], alo[s][2], alo[s][3], bf[s][0], bf[s][1]);
                }
                int ua = u0 + (lane >> 2);
                int qc = qt * 128 + q0 + 2 * (lane & 3);
                *(__half2*)(Lh + ua * L_STRIDE + qc)       = __floats2half2_rn(d0, d1);
                *(__half2*)(Lh + (ua + 8) * L_STRIDE + qc) = __floats2half2_rn(d2, d3);
            }
        }
        __syncthreads();
    }

    // stats: thread owns (u = tid&127, q-half h = tid>>7); y = x*e^x in place
    float* m2 = (float*)(sm + SCR_OFF);          // [2][128]
    float* T2 = m2 + 256;                        // [2][128]
    int u = tid & 127, h = tid >> 7;
    {
        __half2* row = (__half2*)(sm + L_OFF) + (u * (L_STRIDE / 2) + h * 128);
        float m = -1e30f, T = 0.0f;
#pragma unroll 8
        for (int j = 0; j < 128; j++) {
            float2 x = __half22float2(row[j]);
            float e0 = __expf(x.x), e1 = __expf(x.y);
            float y0 = x.x * e0, y1 = x.y * e1;
            m = fmaxf(m, fmaxf(x.x, x.y));
            T += fabsf(y0) + fabsf(y1);
            row[j] = __floats2half2_rn(y0, y1);
        }
        m2[h * 128 + u] = m;
        T2[h * 128 + u] = T;
    }
    __syncthreads();

    if (tid < 128) {
        float m = fmaxf(m2[tid], m2[128 + tid]);
        float T = T2[tid] + T2[128 + tid];
        float vu = g_v[((size_t)b * KK + kidx) * TT + tid];
        g_w[((size_t)b * KK + kidx) * TT + tid] = vu / (T + __expf(m));
    }

    // coalesced copy L -> g_xe (uint2 = 4 halves)
    {
        uint2* dst = (uint2*)(g_xe + ((size_t)(b * KK + kidx) * TT) * QQ);
        const unsigned char* src = sm + L_OFF;
        for (int i = tid; i < 128 * 128; i += 256) {
            int ur = i >> 7, j = i & 127;
            uint2 v = *(const uint2*)(src + ur * (L_STRIDE * 2) + j * 8);
            dst[ur * 128 + j] = v;
        }
    }
}

// ---------------- pass 2: out[b,q,u] = sum_k w[b,k,u] * y[b,k,u,q] ----------------
__global__ __launch_bounds__(256) void pass2() {
    int g = blockIdx.x * 256 + threadIdx.x;      // 65536 threads
    int b  = g >> 15;
    int u  = (g >> 8) & 127;
    int q2 = g & 255;
    const __half2* src = (const __half2*)g_xe + ((size_t)(b * KK) * TT + u) * (QQ / 2) + q2;
    const float* wp = g_w + (size_t)b * KK * TT + u;
    const size_t kstride = (size_t)TT * QQ / 2;
    float2 acc = {0.0f, 0.0f};
#pragma unroll 8
    for (int k = 0; k < KK; k++) {
        float2 f = __half22float2(src[(size_t)k * kstride]);
        float wv = wp[(size_t)k * TT];
        acc.x = fmaf(wv, f.x, acc.x);
        acc.y = fmaf(wv, f.y, acc.y);
    }
    int q = q2 * 2;
    g_acc[((size_t)b * QQ + q) * TT + u]     = acc.x;
    g_acc[((size_t)b * QQ + q + 1) * TT + u] = acc.y;
}

// ---------------- launch ----------------
extern "C" void kernel_launch(void* const* d_in, const int* in_sizes, int n_in,
                              void* d_out, int out_size) {
    const float* q_in = (const float*)d_in[0];
    const float* k_in = (const float*)d_in[1];
    const float* v_in = (const float*)d_in[2];
    const float* Wk   = (const float*)d_in[3];
    const float* Wq   = (const float*)d_in[4];
    const float* Wv   = (const float*)d_in[5];
    const float* Wl   = (const float*)d_in[6];
    const float* Wo   = (const float*)d_in[7];
    float* out = (float*)d_out;

    const int SMEM_G = (128 * 132 + 32 * 132) * 4;   // 84480
    cudaFuncSetAttribute(gemm32, cudaFuncAttributeMaxDynamicSharedMemorySize, SMEM_G);
    cudaFuncSetAttribute(proj3,  cudaFuncAttributeMaxDynamicSharedMemorySize, SMEM_G);
    cudaFuncSetAttribute(pass1,  cudaFuncAttributeMaxDynamicSharedMemorySize, P1_SMEM);

    float* pacc;
    cudaGetSymbolAddress((void**)&pacc, g_acc);

    prep_wl<<<64, 256>>>(Wl);
    proj3<<<dim3(32, 3), 256, SMEM_G>>>(q_in, Wq, k_in, Wk, v_in, Wv);
    pass1<<<BB * KK, 256, P1_SMEM>>>();
    pass2<<<256, 256>>>();
    gemm32<<<32, 256, SMEM_G>>>(pacc, Wo, out);
}

// round 5
// speedup vs baseline: 2.5463x; 1.2239x over previous
#include <cuda_runtime.h>
#include <cuda_fp16.h>
#include <cstdint>

#define BB 2
#define KK 512
#define QQ 512
#define TT 128
#define NREP 4

// ---------------- device scratch ----------------
__device__ float g_k[BB * KK * TT];
__device__ float g_q[BB * QQ * TT];
__device__ float g_v[BB * KK * TT];
__device__ float g_w[BB * KK * TT];                  // per (b,k,u) scale v_u/(T+e^m)
__device__ float g_accr[NREP * BB * QQ * TT];        // k-split partial sums
__device__ __half g_xe[(size_t)BB * KK * TT * QQ];   // 128MB unscaled y = x*e^x
__device__ unsigned char g_wlhi[32768];              // swizzled fp16 Wl hi image
__device__ unsigned char g_wllo[32768];              // swizzled fp16 Wl lo image

// ---------------- helpers ----------------
__device__ __forceinline__ uint32_t smem_u32(const void* p) {
    uint32_t a;
    asm("{ .reg .u64 t; cvta.to.shared.u64 t, %1; cvt.u32.u64 %0, t; }" : "=r"(a) : "l"(p));
    return a;
}
__device__ __forceinline__ void ldsm_x4(uint32_t& r0, uint32_t& r1, uint32_t& r2, uint32_t& r3,
                                        uint32_t addr) {
    asm volatile("ldmatrix.sync.aligned.m8n8.x4.shared.b16 {%0,%1,%2,%3}, [%4];"
                 : "=r"(r0), "=r"(r1), "=r"(r2), "=r"(r3) : "r"(addr));
}
__device__ __forceinline__ void ldsm_x2(uint32_t& r0, uint32_t& r1, uint32_t addr) {
    asm volatile("ldmatrix.sync.aligned.m8n8.x2.shared.b16 {%0,%1}, [%2];"
                 : "=r"(r0), "=r"(r1) : "r"(addr));
}
__device__ __forceinline__ void mma16816(float& d0, float& d1, float& d2, float& d3,
                                         uint32_t a0, uint32_t a1, uint32_t a2, uint32_t a3,
                                         uint32_t b0, uint32_t b1) {
    asm volatile("mma.sync.aligned.m16n8k16.row.col.f32.f16.f16.f32 "
                 "{%0,%1,%2,%3}, {%4,%5,%6,%7}, {%8,%9}, {%0,%1,%2,%3};"
                 : "+f"(d0), "+f"(d1), "+f"(d2), "+f"(d3)
                 : "r"(a0), "r"(a1), "r"(a2), "r"(a3), "r"(b0), "r"(b1));
}

// smem byte layout for pass1 (total 101888 -> 2 CTAs/SM)
#define A_HI_OFF 0
#define A_LO_OFF 32768
#define XY_OFF   65536          // X phase: 128 q-rows x 256B ; Y phase: 128 u-rows x 272B
#define Y_STRIDE 272
#define KRAW_OFF 100352
#define STAT_OFF 100864         // m[128], T[128]
#define P1_SMEM  101888

// ---------------- prep: Wl -> hi/lo fp16, swizzled smem image ----------------
__global__ void prep_wl(const float* __restrict__ Wl) {
    int i = blockIdx.x * 256 + threadIdx.x;
    if (i >= TT * TT) return;
    int u = i >> 7, t = i & 127;
    float w = Wl[i];
    __half hi = __float2half_rn(w);
    __half lo = __float2half_rn(w - __half2float(hi));
    uint32_t byte = (uint32_t)u * 256u + ((((uint32_t)t >> 3) ^ (u & 7)) << 4) + (t & 7) * 2u;
    *(__half*)(g_wlhi + byte) = hi;
    *(__half*)(g_wllo + byte) = lo;
}

// ---------------- fp32 GEMM 32-row tiles: out[r,u] = sum_t in[r,t]*W[u,t] ----------------
__device__ __forceinline__ void gemm32_body(const float* __restrict__ in,
                                            const float* __restrict__ W,
                                            float* __restrict__ out, int r0, int sum4) {
    extern __shared__ float smf[];
    float* sW = smf;                 // [128][132]
    float* sI = smf + 128 * 132;     // [32][132]
    int tid = threadIdx.x;
    for (int i = tid; i < 128 * 128; i += 256) { int u = i >> 7, t = i & 127; sW[u * 132 + t] = W[i]; }
    for (int i = tid; i < 32 * 128;  i += 256) {
        int r = i >> 7, t = i & 127;
        float v;
        if (sum4) {
            const size_t off = (size_t)r0 * 128 + i;
            const size_t st = (size_t)BB * QQ * TT;
            v = in[off] + in[off + st] + in[off + 2 * st] + in[off + 3 * st];
        } else {
            v = in[(size_t)r0 * 128 + i];
        }
        sI[r * 132 + t] = v;
    }
    __syncthreads();
    int tx = tid & 15, ty = tid >> 4;
    float acc[2][8];
#pragma unroll
    for (int i = 0; i < 2; i++)
#pragma unroll
        for (int j = 0; j < 8; j++) acc[i][j] = 0.0f;
    for (int t = 0; t < 128; t += 4) {
        float4 a0 = *(const float4*)&sI[(ty * 2 + 0) * 132 + t];
        float4 a1 = *(const float4*)&sI[(ty * 2 + 1) * 132 + t];
#pragma unroll
        for (int j = 0; j < 8; j++) {
            float4 bv = *(const float4*)&sW[(tx + 16 * j) * 132 + t];
            acc[0][j] = fmaf(a0.x, bv.x, acc[0][j]); acc[0][j] = fmaf(a0.y, bv.y, acc[0][j]);
            acc[0][j] = fmaf(a0.z, bv.z, acc[0][j]); acc[0][j] = fmaf(a0.w, bv.w, acc[0][j]);
            acc[1][j] = fmaf(a1.x, bv.x, acc[1][j]); acc[1][j] = fmaf(a1.y, bv.y, acc[1][j]);
            acc[1][j] = fmaf(a1.z, bv.z, acc[1][j]); acc[1][j] = fmaf(a1.w, bv.w, acc[1][j]);
        }
    }
#pragma unroll
    for (int i = 0; i < 2; i++)
#pragma unroll
        for (int j = 0; j < 8; j++)
            out[(size_t)(r0 + ty * 2 + i) * 128 + tx + 16 * j] = acc[i][j];
}

__global__ __launch_bounds__(256) void gemm_out(const float* __restrict__ W,
                                                float* __restrict__ out) {
    gemm32_body(g_accr, W, out, blockIdx.x * 32, 1);
}

__global__ __launch_bounds__(256) void proj3(const float* __restrict__ qi, const float* __restrict__ Wq,
                                             const float* __restrict__ ki, const float* __restrict__ Wk,
                                             const float* __restrict__ vi, const float* __restrict__ Wv) {
    int r0 = blockIdx.x * 32;
    if (blockIdx.y == 0)      gemm32_body(qi, Wq, g_q, r0, 0);
    else if (blockIdx.y == 1) gemm32_body(ki, Wk, g_k, r0, 0);
    else                      gemm32_body(vi, Wv, g_v, r0, 0);
}

// ---------------- pass 1: CTA per (b,k) ----------------
__global__ __launch_bounds__(256, 2) void pass1() {
    extern __shared__ unsigned char sm[];
    int tid = threadIdx.x, wid = tid >> 5, lane = tid & 31;
    int b = blockIdx.x >> 9, kidx = blockIdx.x & 511;

    // A tiles (pre-swizzled) -> smem
    {
        uint4* ah = (uint4*)(sm + A_HI_OFF);
        uint4* al = (uint4*)(sm + A_LO_OFF);
        const uint4* shp = (const uint4*)g_wlhi;
        const uint4* slp = (const uint4*)g_wllo;
        for (int i = tid; i < 2048; i += 256) { ah[i] = shp[i]; al[i] = slp[i]; }
    }
    // k row -> smem scratch
    float* kraw = (float*)(sm + KRAW_OFF);
    if (tid < 32)
        ((float4*)kraw)[tid] = ((const float4*)(g_k + ((size_t)b * KK + kidx) * TT))[tid];
    __syncthreads();

    // A fragments: warp wid owns u rows [wid*16, wid*16+16), all K=128 (8 k-steps)
    uint32_t ahi[8][4], alo[8][4];
    {
        int u0 = wid * 16;
        int row = u0 + (lane & 7) + ((lane >> 3) & 1) * 8;
        int cpar = (lane >> 4) & 1;
        int r7 = lane & 7;
        uint32_t rbh = smem_u32(sm + A_HI_OFF) + row * 256;
        uint32_t rbl = smem_u32(sm + A_LO_OFF) + row * 256;
#pragma unroll
        for (int s = 0; s < 8; s++) {
            int chunk = 2 * s + cpar;
            uint32_t off = (uint32_t)((chunk ^ r7) << 4);
            ldsm_x4(ahi[s][0], ahi[s][1], ahi[s][2], ahi[s][3], rbh + off);
            ldsm_x4(alo[s][0], alo[s][1], alo[s][2], alo[s][3], rbl + off);
        }
    }

    uint32_t xybase = smem_u32(sm + XY_OFF);
    int u0 = wid * 16;
    int r4 = lane >> 2;          // 0..7
    int c4 = lane & 3;           // 0..3
    // running stats for the two owned u-rows
    float mA = -1e30f, TA = 0.0f, mB = -1e30f, TB = 0.0f;

    for (int qt = 0; qt < 4; qt++) {
        // build X[q][t] = fp16(q * k), swizzled chunks; thread -> (q = tid>>1, half h)
        {
            int q = tid >> 1, h = tid & 1;
            const float4* qrow = (const float4*)(g_q + ((size_t)b * QQ + qt * 128 + q) * TT + h * 64);
            const float4* krow = (const float4*)(kraw + h * 64);
            unsigned char* xrow = sm + XY_OFF + q * 256;
            int q7 = q & 7;
#pragma unroll
            for (int c8 = 0; c8 < 8; c8++) {
                float4 qa = qrow[c8 * 2], qb = qrow[c8 * 2 + 1];
                float4 ka = krow[c8 * 2], kb = krow[c8 * 2 + 1];
                __half2 h0 = __floats2half2_rn(qa.x * ka.x, qa.y * ka.y);
                __half2 h1 = __floats2half2_rn(qa.z * ka.z, qa.w * ka.w);
                __half2 h2 = __floats2half2_rn(qb.x * kb.x, qb.y * kb.y);
                __half2 h3 = __floats2half2_rn(qb.z * kb.z, qb.w * kb.w);
                int chunk = h * 8 + c8;
                uint4 pk;
                pk.x = *(uint32_t*)&h0; pk.y = *(uint32_t*)&h1;
                pk.z = *(uint32_t*)&h2; pk.w = *(uint32_t*)&h3;
                *(uint4*)(xrow + ((chunk ^ q7) << 4)) = pk;
            }
        }
        __syncthreads();

        // MMA + exp epilogue: y for this tile kept in 32 regs
        uint32_t yreg[32];
        {
            int brow7 = lane & 7;
            int bpar = (lane >> 3) & 1;
#pragma unroll 1
            for (int nt = 0; nt < 16; nt++) {
                int q0 = nt * 8;
                int row = q0 + brow7;
                uint32_t rb = xybase + row * 256;
                int r7 = row & 7;
                uint32_t bf[8][2];
#pragma unroll
                for (int s = 0; s < 8; s++) {
                    int chunk = 2 * s + bpar;
                    ldsm_x2(bf[s][0], bf[s][1], rb + ((chunk ^ r7) << 4));
                }
                float d0 = 0, d1 = 0, d2 = 0, d3 = 0;
#pragma unroll
                for (int s = 0; s < 8; s++) {
                    mma16816(d0, d1, d2, d3, ahi[s][0], ahi[s][1], ahi[s][2], ahi[s][3], bf[s][0], bf[s][1]);
                    mma16816(d0, d1, d2, d3, alo[s][0], alo[s][1], alo[s][2], alo[s][3], bf[s][0], bf[s][1]);
                }
                float y0 = d0 * __expf(d0), y1 = d1 * __expf(d1);
                float y2 = d2 * __expf(d2), y3 = d3 * __expf(d3);
                mA = fmaxf(mA, fmaxf(d0, d1));
                mB = fmaxf(mB, fmaxf(d2, d3));
                TA += fabsf(y0) + fabsf(y1);
                TB += fabsf(y2) + fabsf(y3);
                __half2 p0 = __floats2half2_rn(y0, y1);
                __half2 p1 = __floats2half2_rn(y2, y3);
                yreg[nt * 2]     = *(uint32_t*)&p0;
                yreg[nt * 2 + 1] = *(uint32_t*)&p1;
            }
        }
        __syncthreads();   // all warps done reading X

        // flush y regs -> XY (u-major, stride 272B, conflict-free)
        {
            unsigned char* base = sm + XY_OFF;
#pragma unroll
            for (int nt = 0; nt < 16; nt++) {
                int qc = nt * 8 + 2 * c4;          // tile-local column (half index)
                *(uint32_t*)(base + (u0 + r4) * Y_STRIDE + qc * 2)     = yreg[nt * 2];
                *(uint32_t*)(base + (u0 + 8 + r4) * Y_STRIDE + qc * 2) = yreg[nt * 2 + 1];
            }
        }
        __syncthreads();

        // coalesced copy XY -> g_xe[b,k][u][qt*128..]
        {
            uint4* dst = (uint4*)(g_xe + ((size_t)(b * KK + kidx) * TT) * QQ);
            for (int idx = tid; idx < 2048; idx += 256) {
                int u = idx >> 4, c16 = idx & 15;
                uint4 v = *(const uint4*)(sm + XY_OFF + u * Y_STRIDE + c16 * 16);
                dst[u * 64 + qt * 16 + c16] = v;
            }
        }
        __syncthreads();
    }

    // reduce stats over the 4 lanes of each quad
    mA = fmaxf(mA, __shfl_xor_sync(0xFFFFFFFFu, mA, 1));
    mA = fmaxf(mA, __shfl_xor_sync(0xFFFFFFFFu, mA, 2));
    TA += __shfl_xor_sync(0xFFFFFFFFu, TA, 1);
    TA += __shfl_xor_sync(0xFFFFFFFFu, TA, 2);
    mB = fmaxf(mB, __shfl_xor_sync(0xFFFFFFFFu, mB, 1));
    mB = fmaxf(mB, __shfl_xor_sync(0xFFFFFFFFu, mB, 2));
    TB += __shfl_xor_sync(0xFFFFFFFFu, TB, 1);
    TB += __shfl_xor_sync(0xFFFFFFFFu, TB, 2);

    float* smm = (float*)(sm + STAT_OFF);
    float* smt = smm + 128;
    if (c4 == 0) {
        smm[u0 + r4] = mA;      smt[u0 + r4] = TA;
        smm[u0 + 8 + r4] = mB;  smt[u0 + 8 + r4] = TB;
    }
    __syncthreads();

    if (tid < 128) {
        float m = smm[tid], T = smt[tid];
        float vu = g_v[((size_t)b * KK + kidx) * TT + tid];
        g_w[((size_t)b * KK + kidx) * TT + tid] = vu / (T + __expf(m));
    }
}

// ---------------- pass 2: partial out over k-chunk; 4 replicas ----------------
__global__ __launch_bounds__(256) void pass2() {
    int g = blockIdx.x * 256 + threadIdx.x;      // 65536 threads per chunk
    int kc = blockIdx.y;                          // 0..3
    int b  = g >> 15;
    int u  = (g >> 8) & 127;
    int q2 = g & 255;
    const __half2* src = (const __half2*)g_xe
        + ((size_t)((b * KK + kc * 128)) * TT + u) * (QQ / 2) + q2;
    const float* wp = g_w + (size_t)b * KK * TT + (size_t)kc * 128 * TT + u;
    const size_t kstride = (size_t)TT * QQ / 2;
    float2 acc = {0.0f, 0.0f};
#pragma unroll 8
    for (int k = 0; k < 128; k++) {
        float2 f = __half22float2(src[(size_t)k * kstride]);
        float wv = wp[(size_t)k * TT];
        acc.x = fmaf(wv, f.x, acc.x);
        acc.y = fmaf(wv, f.y, acc.y);
    }
    int q = q2 * 2;
    float* dst = g_accr + (size_t)kc * BB * QQ * TT;
    dst[((size_t)b * QQ + q) * TT + u]     = acc.x;
    dst[((size_t)b * QQ + q + 1) * TT + u] = acc.y;
}

// ---------------- launch ----------------
extern "C" void kernel_launch(void* const* d_in, const int* in_sizes, int n_in,
                              void* d_out, int out_size) {
    const float* q_in = (const float*)d_in[0];
    const float* k_in = (const float*)d_in[1];
    const float* v_in = (const float*)d_in[2];
    const float* Wk   = (const float*)d_in[3];
    const float* Wq   = (const float*)d_in[4];
    const float* Wv   = (const float*)d_in[5];
    const float* Wl   = (const float*)d_in[6];
    const float* Wo   = (const float*)d_in[7];
    float* out = (float*)d_out;

    const int SMEM_G = (128 * 132 + 32 * 132) * 4;   // 84480
    cudaFuncSetAttribute(gemm_out, cudaFuncAttributeMaxDynamicSharedMemorySize, SMEM_G);
    cudaFuncSetAttribute(proj3,    cudaFuncAttributeMaxDynamicSharedMemorySize, SMEM_G);
    cudaFuncSetAttribute(pass1,    cudaFuncAttributeMaxDynamicSharedMemorySize, P1_SMEM);

    prep_wl<<<64, 256>>>(Wl);
    proj3<<<dim3(32, 3), 256, SMEM_G>>>(q_in, Wq, k_in, Wk, v_in, Wv);
    pass1<<<BB * KK, 256, P1_SMEM>>>();
    pass2<<<dim3(256, NREP), 256>>>();
    gemm_out<<<32, 256, SMEM_G>>>(Wo, out);
}

// round 7
// speedup vs baseline: 2.9112x; 1.1433x over previous
#include <cuda_runtime.h>
#include <cuda_fp16.h>
#include <cstdint>

#define BB 2
#define KK 512
#define QQ 512
#define TT 128
#define NREP 8

// ---------------- device scratch ----------------
__device__ float g_k[BB * KK * TT];
__device__ float g_q[BB * QQ * TT];
__device__ float g_v[BB * KK * TT];
__device__ float g_w[BB * KK * TT];                  // per (b,k,u) scale v_u/(T+e^m)
__device__ float g_accr[NREP * BB * QQ * TT];        // k-split partial sums
__device__ __half g_xe[(size_t)BB * KK * TT * QQ];   // 128MB unscaled y = x*e^x
__device__ unsigned char g_wlhi[32768];              // swizzled fp16 Wl image

// ---------------- helpers ----------------
__device__ __forceinline__ uint32_t smem_u32(const void* p) {
    uint32_t a;
    asm("{ .reg .u64 t; cvta.to.shared.u64 t, %1; cvt.u32.u64 %0, t; }" : "=r"(a) : "l"(p));
    return a;
}
__device__ __forceinline__ void ldsm_x4(uint32_t& r0, uint32_t& r1, uint32_t& r2, uint32_t& r3,
                                        uint32_t addr) {
    asm volatile("ldmatrix.sync.aligned.m8n8.x4.shared.b16 {%0,%1,%2,%3}, [%4];"
                 : "=r"(r0), "=r"(r1), "=r"(r2), "=r"(r3) : "r"(addr));
}
__device__ __forceinline__ void mma16816(float& d0, float& d1, float& d2, float& d3,
                                         uint32_t a0, uint32_t a1, uint32_t a2, uint32_t a3,
                                         uint32_t b0, uint32_t b1) {
    asm volatile("mma.sync.aligned.m16n8k16.row.col.f32.f16.f16.f32 "
                 "{%0,%1,%2,%3}, {%4,%5,%6,%7}, {%8,%9}, {%0,%1,%2,%3};"
                 : "+f"(d0), "+f"(d1), "+f"(d2), "+f"(d3)
                 : "r"(a0), "r"(a1), "r"(a2), "r"(a3), "r"(b0), "r"(b1));
}

// smem byte layout for pass1 (total 99840 -> 2 CTAs/SM)
#define A_OFF    0          // 32KB: Wl hi tile; reused as y staging after frag load
#define X0_OFF   32768      // 32KB X buffer 0
#define X1_OFF   65536      // 32KB X buffer 1
#define KRAW_OFF 98304      // 512B
#define STAT_OFF 98816      // m[128], T[128] = 1KB
#define P1_SMEM  99840

// ---------------- prep: Wl -> fp16, swizzled smem image ----------------
__global__ void prep_wl(const float* __restrict__ Wl) {
    int i = blockIdx.x * 256 + threadIdx.x;
    if (i >= TT * TT) return;
    int u = i >> 7, t = i & 127;
    uint32_t byte = (uint32_t)u * 256u + ((((uint32_t)t >> 3) ^ (u & 7)) << 4) + (t & 7) * 2u;
    *(__half*)(g_wlhi + byte) = __float2half_rn(Wl[i]);
}

// ---------------- fp32 GEMM 32-row tiles: out[r,u] = sum_t in[r,t]*W[u,t] ----------------
__device__ __forceinline__ void gemm32_body(const float* __restrict__ in,
                                            const float* __restrict__ W,
                                            float* __restrict__ out, int r0, int sum8) {
    extern __shared__ float smf[];
    float* sW = smf;                 // [128][132]
    float* sI = smf + 128 * 132;     // [32][132]
    int tid = threadIdx.x;
    for (int i = tid; i < 128 * 128; i += 256) { int u = i >> 7, t = i & 127; sW[u * 132 + t] = W[i]; }
    for (int i = tid; i < 32 * 128;  i += 256) {
        int r = i >> 7, t = i & 127;
        float v;
        if (sum8) {
            const size_t off = (size_t)r0 * 128 + i;
            const size_t st = (size_t)BB * QQ * TT;
            v = 0.0f;
#pragma unroll
            for (int rr = 0; rr < NREP; rr++) v += in[off + (size_t)rr * st];
        } else {
            v = in[(size_t)r0 * 128 + i];
        }
        sI[r * 132 + t] = v;
    }
    __syncthreads();
    int tx = tid & 15, ty = tid >> 4;
    float acc[2][8];
#pragma unroll
    for (int i = 0; i < 2; i++)
#pragma unroll
        for (int j = 0; j < 8; j++) acc[i][j] = 0.0f;
    for (int t = 0; t < 128; t += 4) {
        float4 a0 = *(const float4*)&sI[(ty * 2 + 0) * 132 + t];
        float4 a1 = *(const float4*)&sI[(ty * 2 + 1) * 132 + t];
#pragma unroll
        for (int j = 0; j < 8; j++) {
            float4 bv = *(const float4*)&sW[(tx + 16 * j) * 132 + t];
            acc[0][j] = fmaf(a0.x, bv.x, acc[0][j]); acc[0][j] = fmaf(a0.y, bv.y, acc[0][j]);
            acc[0][j] = fmaf(a0.z, bv.z, acc[0][j]); acc[0][j] = fmaf(a0.w, bv.w, acc[0][j]);
            acc[1][j] = fmaf(a1.x, bv.x, acc[1][j]); acc[1][j] = fmaf(a1.y, bv.y, acc[1][j]);
            acc[1][j] = fmaf(a1.z, bv.z, acc[1][j]); acc[1][j] = fmaf(a1.w, bv.w, acc[1][j]);
        }
    }
#pragma unroll
    for (int i = 0; i < 2; i++)
#pragma unroll
        for (int j = 0; j < 8; j++)
            out[(size_t)(r0 + ty * 2 + i) * 128 + tx + 16 * j] = acc[i][j];
}

__global__ __launch_bounds__(256) void gemm_out(const float* __restrict__ W,
                                                float* __restrict__ out) {
    gemm32_body(g_accr, W, out, blockIdx.x * 32, 1);
}

__global__ __launch_bounds__(256) void proj3(const float* __restrict__ qi, const float* __restrict__ Wq,
                                             const float* __restrict__ ki, const float* __restrict__ Wk,
                                             const float* __restrict__ vi, const float* __restrict__ Wv) {
    int r0 = blockIdx.x * 32;
    if (blockIdx.y == 0)      gemm32_body(qi, Wq, g_q, r0, 0);
    else if (blockIdx.y == 1) gemm32_body(ki, Wk, g_k, r0, 0);
    else                      gemm32_body(vi, Wv, g_v, r0, 0);
}

// ---------------- build X tile: X[q][t] = fp16(q * k), swizzled chunks ----------------
__device__ __forceinline__ void build_x(unsigned char* sm, int b, int qt, int buf,
                                        const float* kraw, int tid) {
    int q = tid >> 1, h = tid & 1;
    const float4* qrow = (const float4*)(g_q + ((size_t)b * QQ + qt * 128 + q) * TT + h * 64);
    const float4* krow = (const float4*)(kraw + h * 64);
    unsigned char* xrow = sm + (buf ? X1_OFF : X0_OFF) + q * 256;
    int q7 = q & 7;
#pragma unroll
    for (int c8 = 0; c8 < 8; c8++) {
        float4 qa = qrow[c8 * 2], qb = qrow[c8 * 2 + 1];
        float4 ka = krow[c8 * 2], kb = krow[c8 * 2 + 1];
        __half2 h0 = __floats2half2_rn(qa.x * ka.x, qa.y * ka.y);
        __half2 h1 = __floats2half2_rn(qa.z * ka.z, qa.w * ka.w);
        __half2 h2 = __floats2half2_rn(qb.x * kb.x, qb.y * kb.y);
        __half2 h3 = __floats2half2_rn(qb.z * kb.z, qb.w * kb.w);
        int chunk = h * 8 + c8;
        uint4 pk;
        pk.x = *(uint32_t*)&h0; pk.y = *(uint32_t*)&h1;
        pk.z = *(uint32_t*)&h2; pk.w = *(uint32_t*)&h3;
        *(uint4*)(xrow + ((chunk ^ q7) << 4)) = pk;
    }
}

// ---------------- pass 1: CTA per (b,k) ----------------
__global__ __launch_bounds__(256, 2) void pass1() {
    extern __shared__ unsigned char sm[];
    int tid = threadIdx.x, wid = tid >> 5, lane = tid & 31;
    int b = blockIdx.x >> 9, kidx = blockIdx.x & 511;

    // A tile (pre-swizzled fp16 Wl) -> smem
    {
        uint4* ah = (uint4*)(sm + A_OFF);
        const uint4* shp = (const uint4*)g_wlhi;
        for (int i = tid; i < 2048; i += 256) ah[i] = shp[i];
    }
    float* kraw = (float*)(sm + KRAW_OFF);
    if (tid < 32)
        ((float4*)kraw)[tid] = ((const float4*)(g_k + ((size_t)b * KK + kidx) * TT))[tid];
    __syncthreads();

    // A fragments: warp wid owns u-rows [wid*16, +16), K=128 (8 k-steps)
    int u0 = wid * 16;
    uint32_t ahi[8][4];
    {
        int row = u0 + (lane & 7) + ((lane >> 3) & 1) * 8;
        int cpar = (lane >> 4) & 1;
        int r7 = lane & 7;
        uint32_t rbh = smem_u32(sm + A_OFF) + row * 256;
#pragma unroll
        for (int s = 0; s < 8; s++) {
            int chunk = 2 * s + cpar;
            ldsm_x4(ahi[s][0], ahi[s][1], ahi[s][2], ahi[s][3], rbh + ((chunk ^ r7) << 4));
        }
    }
    // build X0 for qt=0 (A-smem now dead; safe to reuse as y staging after this point)
    build_x(sm, b, 0, 0, kraw, tid);
    __syncthreads();

    int r4 = lane >> 2, c4 = lane & 3;
    float mA = -1e30f, TA = 0.0f, mB = -1e30f, TB = 0.0f;
    uint32_t xb0 = smem_u32(sm);
    uint4* dst = (uint4*)(g_xe + ((size_t)(b * KK + kidx) * TT) * QQ);

    for (int qt = 0; qt < 4; qt++) {
        int buf = qt & 1;
        uint32_t xb = xb0 + (buf ? X1_OFF : X0_OFF);
        // MMA + exp epilogue + inline flush to A region (warp-private u-rows)
        {
            int brow7 = lane & 7;
            int bgrp = lane >> 3;         // 0..3
            int uA = u0 + r4, uB = u0 + 8 + r4;
            unsigned char* yrA = sm + A_OFF + uA * 256;
            unsigned char* yrB = sm + A_OFF + uB * 256;
            int rotA = uA * 16, rotB = uB * 16;
#pragma unroll 1
            for (int nt = 0; nt < 16; nt++) {
                int q0 = nt * 8;
                int row = q0 + brow7;
                uint32_t rb = xb + row * 256;
                int r7 = row & 7;
                uint32_t bf[8][2];
#pragma unroll
                for (int sp = 0; sp < 4; sp++) {
                    int chunk = 4 * sp + bgrp;
                    uint32_t t0, t1, t2, t3;
                    ldsm_x4(t0, t1, t2, t3, rb + ((chunk ^ r7) << 4));
                    bf[2 * sp][0] = t0; bf[2 * sp][1] = t1;
                    bf[2 * sp + 1][0] = t2; bf[2 * sp + 1][1] = t3;
                }
                float d0 = 0, d1 = 0, d2 = 0, d3 = 0;
#pragma unroll
                for (int s = 0; s < 8; s++)
                    mma16816(d0, d1, d2, d3, ahi[s][0], ahi[s][1], ahi[s][2], ahi[s][3],
                             bf[s][0], bf[s][1]);
                float y0 = d0 * __expf(d0), y1 = d1 * __expf(d1);
                float y2 = d2 * __expf(d2), y3 = d3 * __expf(d3);
                mA = fmaxf(mA, fmaxf(d0, d1));
                mB = fmaxf(mB, fmaxf(d2, d3));
                TA += fabsf(y0) + fabsf(y1);
                TB += fabsf(y2) + fabsf(y3);
                __half2 p0 = __floats2half2_rn(y0, y1);
                __half2 p1 = __floats2half2_rn(y2, y3);
                int qb = nt * 16 + 4 * c4;           // byte within 256B row
                *(uint32_t*)(yrA + ((qb + rotA) & 255)) = *(uint32_t*)&p0;
                *(uint32_t*)(yrB + ((qb + rotB) & 255)) = *(uint32_t*)&p1;
            }
        }
        __syncthreads();

        // build next X + copy y staging -> g_xe (fused phase, disjoint regions)
        if (qt < 3) build_x(sm, b, qt + 1, buf ^ 1, kraw, tid);
        for (int idx = tid; idx < 2048; idx += 256) {
            int uu = idx >> 4, c = idx & 15;
            uint4 v = *(const uint4*)(sm + A_OFF + uu * 256 + ((c * 16 + uu * 16) & 255));
            dst[uu * 64 + qt * 16 + c] = v;
        }
        __syncthreads();
    }

    // reduce stats over the 4 lanes of each quad
    mA = fmaxf(mA, __shfl_xor_sync(0xFFFFFFFFu, mA, 1));
    mA = fmaxf(mA, __shfl_xor_sync(0xFFFFFFFFu, mA, 2));
    TA += __shfl_xor_sync(0xFFFFFFFFu, TA, 1);
    TA += __shfl_xor_sync(0xFFFFFFFFu, TA, 2);
    mB = fmaxf(mB, __shfl_xor_sync(0xFFFFFFFFu, mB, 1));
    mB = fmaxf(mB, __shfl_xor_sync(0xFFFFFFFFu, mB, 2));
    TB += __shfl_xor_sync(0xFFFFFFFFu, TB, 1);
    TB += __shfl_xor_sync(0xFFFFFFFFu, TB, 2);

    float* smm = (float*)(sm + STAT_OFF);
    float* smt = smm + 128;
    if (c4 == 0) {
        smm[u0 + r4] = mA;      smt[u0 + r4] = TA;
        smm[u0 + 8 + r4] = mB;  smt[u0 + 8 + r4] = TB;
    }
    __syncthreads();

    if (tid < 128) {
        float m = smm[tid], T = smt[tid];
        float vu = g_v[((size_t)b * KK + kidx) * TT + tid];
        g_w[((size_t)b * KK + kidx) * TT + tid] = vu / (T + __expf(m));
    }
}

// ---------------- pass 2: partial out over k-chunk of 64; 8 replicas ----------------
// grid: (32, BB*NREP) -> 8192 threads per (b,kc) slice: u in [0,128), qg in [0,64)
__global__ __launch_bounds__(256) void pass2() {
    int bykc = blockIdx.y;                       // b*8 + kc
    int b = bykc >> 3, kc = bykc & 7;
    int s = blockIdx.x * 256 + threadIdx.x;      // 8192 per slice
    int qg = s & 63, u = s >> 6;                 // u in [0,128)
    const uint4* src = (const uint4*)(g_xe + ((size_t)(b * KK + kc * 64) * TT + u) * QQ) + qg;
    const float* wp = g_w + ((size_t)b * KK + (size_t)kc * 64) * TT + u;
    const size_t kstride = (size_t)TT * QQ / 8;  // uint4 step per k
    float acc[8];
#pragma unroll
    for (int j = 0; j < 8; j++) acc[j] = 0.0f;
#pragma unroll 4
    for (int k = 0; k < 64; k++) {
        uint4 yv = src[(size_t)k * kstride];
        float wv = wp[(size_t)k * TT];
        float2 f0 = __half22float2(*(__half2*)&yv.x);
        float2 f1 = __half22float2(*(__half2*)&yv.y);
        float2 f2 = __half22float2(*(__half2*)&yv.z);
        float2 f3 = __half22float2(*(__half2*)&yv.w);
        acc[0] = fmaf(wv, f0.x, acc[0]); acc[1] = fmaf(wv, f0.y, acc[1]);
        acc[2] = fmaf(wv, f1.x, acc[2]); acc[3] = fmaf(wv, f1.y, acc[3]);
        acc[4] = fmaf(wv, f2.x, acc[4]); acc[5] = fmaf(wv, f2.y, acc[5]);
        acc[6] = fmaf(wv, f3.x, acc[6]); acc[7] = fmaf(wv, f3.y, acc[7]);
    }
    float* dstp = g_accr + (size_t)kc * BB * QQ * TT;
    int q0 = qg * 8;
#pragma unroll
    for (int j = 0; j < 8; j++)
        dstp[((size_t)b * QQ + q0 + j) * TT + u] = acc[j];
}

// ---------------- launch ----------------
extern "C" void kernel_launch(void* const* d_in, const int* in_sizes, int n_in,
                              void* d_out, int out_size) {
    const float* q_in = (const float*)d_in[0];
    const float* k_in = (const float*)d_in[1];
    const float* v_in = (const float*)d_in[2];
    const float* Wk   = (const float*)d_in[3];
    const float* Wq   = (const float*)d_in[4];
    const float* Wv   = (const float*)d_in[5];
    const float* Wl   = (const float*)d_in[6];
    const float* Wo   = (const float*)d_in[7];
    float* out = (float*)d_out;

    const int SMEM_G = (128 * 132 + 32 * 132) * 4;   // 84480
    cudaFuncSetAttribute(gemm_out, cudaFuncAttributeMaxDynamicSharedMemorySize, SMEM_G);
    cudaFuncSetAttribute(proj3,    cudaFuncAttributeMaxDynamicSharedMemorySize, SMEM_G);
    cudaFuncSetAttribute(pass1,    cudaFuncAttributeMaxDynamicSharedMemorySize, P1_SMEM);

    prep_wl<<<64, 256>>>(Wl);
    proj3<<<dim3(32, 3), 256, SMEM_G>>>(q_in, Wq, k_in, Wk, v_in, Wv);
    pass1<<<BB * KK, 256, P1_SMEM>>>();
    pass2<<<dim3(32, BB * NREP), 256>>>();
    gemm_out<<<32, 256, SMEM_G>>>(Wo, out);
}

// round 8
// speedup vs baseline: 4.0308x; 1.3846x over previous
#include <cuda_runtime.h>
#include <cuda_fp16.h>
#include <cstdint>

#define BB 2
#define KK 512
#define QQ 512
#define TT 128
#define NREP 16

// ---------------- device scratch ----------------
__device__ float g_k[BB * KK * TT];
__device__ float g_q[BB * QQ * TT];
__device__ float g_v[BB * KK * TT];
__device__ float g_w[BB * KK * TT];                  // per (b,k,u) scale v_u/(T+e^m)
__device__ float g_accr[NREP * BB * QQ * TT];        // k-split partial sums
__device__ __half g_xe[(size_t)BB * KK * TT * QQ];   // 128MB unscaled y = x*e^x
__device__ unsigned char g_ak[(size_t)BB * KK * 32768];  // 32MB swizzled fp16 Wl*k images
__device__ unsigned char g_qh[BB * 4 * 32768];           // 256KB swizzled fp16 q tiles

// ---------------- helpers ----------------
__device__ __forceinline__ uint32_t smem_u32(const void* p) {
    uint32_t a;
    asm("{ .reg .u64 t; cvta.to.shared.u64 t, %1; cvt.u32.u64 %0, t; }" : "=r"(a) : "l"(p));
    return a;
}
__device__ __forceinline__ void ldsm_x4(uint32_t& r0, uint32_t& r1, uint32_t& r2, uint32_t& r3,
                                        uint32_t addr) {
    asm volatile("ldmatrix.sync.aligned.m8n8.x4.shared.b16 {%0,%1,%2,%3}, [%4];"
                 : "=r"(r0), "=r"(r1), "=r"(r2), "=r"(r3) : "r"(addr));
}
__device__ __forceinline__ void mma16816(float& d0, float& d1, float& d2, float& d3,
                                         uint32_t a0, uint32_t a1, uint32_t a2, uint32_t a3,
                                         uint32_t b0, uint32_t b1) {
    asm volatile("mma.sync.aligned.m16n8k16.row.col.f32.f16.f16.f32 "
                 "{%0,%1,%2,%3}, {%4,%5,%6,%7}, {%8,%9}, {%0,%1,%2,%3};"
                 : "+f"(d0), "+f"(d1), "+f"(d2), "+f"(d3)
                 : "r"(a0), "r"(a1), "r"(a2), "r"(a3), "r"(b0), "r"(b1));
}
__device__ __forceinline__ void cp16(uint32_t smem, const void* g) {
    asm volatile("cp.async.cg.shared.global [%0], [%1], 16;" :: "r"(smem), "l"(g));
}
#define CP_COMMIT() asm volatile("cp.async.commit_group;" ::: "memory")
#define CP_WAIT(N)  asm volatile("cp.async.wait_group %0;" :: "n"(N) : "memory")

// smem byte layout for pass1 (total 99328 -> 2 CTAs/SM)
#define A_OFF    0          // 32KB: A_k image; reused as y staging after frag load
#define X0_OFF   32768      // 32KB X buffer 0
#define X1_OFF   65536      // 32KB X buffer 1
#define STAT_OFF 98304      // m[128], T[128] = 1KB
#define P1_SMEM  99328

// ---------------- prep: build swizzled fp16 images ----------------
// blocks [0, BB*KK): A_k[u,t] = fp16(Wl[u,t] * k[b,k,t])
// blocks [BB*KK, BB*KK+8): q tiles: fp16(q[b, qt*128+q, t])
__global__ __launch_bounds__(256) void prep_images(const float* __restrict__ Wl) {
    int blk = blockIdx.x;
    int tid = threadIdx.x;
    int r = tid >> 1, h = tid & 1;
    int r7 = r & 7;
    if (blk < BB * KK) {
        int b = blk >> 9, k = blk & 511;
        const float4* wrow = (const float4*)(Wl + (size_t)r * TT + h * 64);
        const float4* krow = (const float4*)(g_k + ((size_t)b * KK + k) * TT + h * 64);
        unsigned char* arow = g_ak + (size_t)blk * 32768 + r * 256;
#pragma unroll
        for (int c8 = 0; c8 < 8; c8++) {
            float4 qa = wrow[c8 * 2], qb = wrow[c8 * 2 + 1];
            float4 ka = krow[c8 * 2], kb = krow[c8 * 2 + 1];
            __half2 h0 = __floats2half2_rn(qa.x * ka.x, qa.y * ka.y);
            __half2 h1 = __floats2half2_rn(qa.z * ka.z, qa.w * ka.w);
            __half2 h2 = __floats2half2_rn(qb.x * kb.x, qb.y * kb.y);
            __half2 h3 = __floats2half2_rn(qb.z * kb.z, qb.w * kb.w);
            int chunk = h * 8 + c8;
            uint4 pk;
            pk.x = *(uint32_t*)&h0; pk.y = *(uint32_t*)&h1;
            pk.z = *(uint32_t*)&h2; pk.w = *(uint32_t*)&h3;
            *(uint4*)(arow + ((chunk ^ r7) << 4)) = pk;
        }
    } else {
        int i = blk - BB * KK;            // 0..7: b = i>>2, qt = i&3
        int b = i >> 2, qt = i & 3;
        const float4* qrow = (const float4*)(g_q + ((size_t)b * QQ + qt * 128 + r) * TT + h * 64);
        unsigned char* xrow = g_qh + (size_t)i * 32768 + r * 256;
#pragma unroll
        for (int c8 = 0; c8 < 8; c8++) {
            float4 qa = qrow[c8 * 2], qb = qrow[c8 * 2 + 1];
            __half2 h0 = __floats2half2_rn(qa.x, qa.y);
            __half2 h1 = __floats2half2_rn(qa.z, qa.w);
            __half2 h2 = __floats2half2_rn(qb.x, qb.y);
            __half2 h3 = __floats2half2_rn(qb.z, qb.w);
            int chunk = h * 8 + c8;
            uint4 pk;
            pk.x = *(uint32_t*)&h0; pk.y = *(uint32_t*)&h1;
            pk.z = *(uint32_t*)&h2; pk.w = *(uint32_t*)&h3;
            *(uint4*)(xrow + ((chunk ^ r7) << 4)) = pk;
        }
    }
}

// ---------------- fp32 GEMM 32-row tiles: out[r,u] = sum_t in[r,t]*W[u,t] ----------------
__device__ __forceinline__ void gemm32_body(const float* __restrict__ in,
                                            const float* __restrict__ W,
                                            float* __restrict__ out, int r0, int sumrep) {
    extern __shared__ float smf[];
    float* sW = smf;                 // [128][132]
    float* sI = smf + 128 * 132;     // [32][132]
    int tid = threadIdx.x;
    for (int i = tid; i < 128 * 128; i += 256) { int u = i >> 7, t = i & 127; sW[u * 132 + t] = W[i]; }
    for (int i = tid; i < 32 * 128;  i += 256) {
        int r = i >> 7, t = i & 127;
        float v;
        if (sumrep) {
            const size_t off = (size_t)r0 * 128 + i;
            const size_t st = (size_t)BB * QQ * TT;
            v = 0.0f;
#pragma unroll
            for (int rr = 0; rr < NREP; rr++) v += in[off + (size_t)rr * st];
        } else {
            v = in[(size_t)r0 * 128 + i];
        }
        sI[r * 132 + t] = v;
    }
    __syncthreads();
    int tx = tid & 15, ty = tid >> 4;
    float acc[2][8];
#pragma unroll
    for (int i = 0; i < 2; i++)
#pragma unroll
        for (int j = 0; j < 8; j++) acc[i][j] = 0.0f;
    for (int t = 0; t < 128; t += 4) {
        float4 a0 = *(const float4*)&sI[(ty * 2 + 0) * 132 + t];
        float4 a1 = *(const float4*)&sI[(ty * 2 + 1) * 132 + t];
#pragma unroll
        for (int j = 0; j < 8; j++) {
            float4 bv = *(const float4*)&sW[(tx + 16 * j) * 132 + t];
            acc[0][j] = fmaf(a0.x, bv.x, acc[0][j]); acc[0][j] = fmaf(a0.y, bv.y, acc[0][j]);
            acc[0][j] = fmaf(a0.z, bv.z, acc[0][j]); acc[0][j] = fmaf(a0.w, bv.w, acc[0][j]);
            acc[1][j] = fmaf(a1.x, bv.x, acc[1][j]); acc[1][j] = fmaf(a1.y, bv.y, acc[1][j]);
            acc[1][j] = fmaf(a1.z, bv.z, acc[1][j]); acc[1][j] = fmaf(a1.w, bv.w, acc[1][j]);
        }
    }
#pragma unroll
    for (int i = 0; i < 2; i++)
#pragma unroll
        for (int j = 0; j < 8; j++)
            out[(size_t)(r0 + ty * 2 + i) * 128 + tx + 16 * j] = acc[i][j];
}

__global__ __launch_bounds__(256) void gemm_out(const float* __restrict__ W,
                                                float* __restrict__ out) {
    gemm32_body(g_accr, W, out, blockIdx.x * 32, 1);
}

__global__ __launch_bounds__(256) void proj3(const float* __restrict__ qi, const float* __restrict__ Wq,
                                             const float* __restrict__ ki, const float* __restrict__ Wk,
                                             const float* __restrict__ vi, const float* __restrict__ Wv) {
    int r0 = blockIdx.x * 32;
    if (blockIdx.y == 0)      gemm32_body(qi, Wq, g_q, r0, 0);
    else if (blockIdx.y == 1) gemm32_body(ki, Wk, g_k, r0, 0);
    else                      gemm32_body(vi, Wv, g_v, r0, 0);
}

// ---------------- pass 1: CTA per (b,k) ----------------
__global__ __launch_bounds__(256, 2) void pass1() {
    extern __shared__ unsigned char sm[];
    int tid = threadIdx.x, wid = tid >> 5, lane = tid & 31;
    int b = blockIdx.x >> 9, kidx = blockIdx.x & 511;
    uint32_t smb = smem_u32(sm);

    // group 0: A_k image + X0 (qt0); group 1: X1 (qt1)
    {
        const uint4* gak = (const uint4*)(g_ak + (size_t)blockIdx.x * 32768);
        const uint4* gq0 = (const uint4*)(g_qh + (size_t)(b * 4 + 0) * 32768);
        const uint4* gq1 = (const uint4*)(g_qh + (size_t)(b * 4 + 1) * 32768);
        for (int i = tid; i < 2048; i += 256) {
            cp16(smb + A_OFF + i * 16, gak + i);
            cp16(smb + X0_OFF + i * 16, gq0 + i);
        }
        CP_COMMIT();
        for (int i = tid; i < 2048; i += 256) cp16(smb + X1_OFF + i * 16, gq1 + i);
        CP_COMMIT();
    }
    CP_WAIT(1);
    __syncthreads();

    // A fragments: warp wid owns u-rows [wid*16, +16), K=128 (8 k-steps)
    int u0 = wid * 16;
    uint32_t ahi[8][4];
    {
        int row = u0 + (lane & 7) + ((lane >> 3) & 1) * 8;
        int cpar = (lane >> 4) & 1;
        int r7 = lane & 7;
        uint32_t rbh = smb + A_OFF + row * 256;
#pragma unroll
        for (int s = 0; s < 8; s++) {
            int chunk = 2 * s + cpar;
            ldsm_x4(ahi[s][0], ahi[s][1], ahi[s][2], ahi[s][3], rbh + ((chunk ^ r7) << 4));
        }
    }
    __syncthreads();   // A region now free for y staging

    int r4 = lane >> 2, c4 = lane & 3;
    float mA = -1e30f, TA = 0.0f, mB = -1e30f, TB = 0.0f;
    uint4* dst = (uint4*)(g_xe + ((size_t)(b * KK + kidx) * TT) * QQ);

    for (int qt = 0; qt < 4; qt++) {
        int buf = qt & 1;
        uint32_t xb = smb + (buf ? X1_OFF : X0_OFF);
        // MMA + exp epilogue + inline flush to A region (warp-private u-rows)
        {
            int brow7 = lane & 7;
            int bgrp = lane >> 3;         // 0..3
            int uA = u0 + r4, uB = u0 + 8 + r4;
            unsigned char* yrA = sm + A_OFF + uA * 256;
            unsigned char* yrB = sm + A_OFF + uB * 256;
            int rotA = uA * 16, rotB = uB * 16;
#pragma unroll 1
            for (int nt = 0; nt < 16; nt++) {
                int q0 = nt * 8;
                int row = q0 + brow7;
                uint32_t rb = xb + row * 256;
                int r7 = row & 7;
                uint32_t bf[8][2];
#pragma unroll
                for (int sp = 0; sp < 4; sp++) {
                    int chunk = 4 * sp + bgrp;
                    uint32_t t0, t1, t2, t3;
                    ldsm_x4(t0, t1, t2, t3, rb + ((chunk ^ r7) << 4));
                    bf[2 * sp][0] = t0; bf[2 * sp][1] = t1;
                    bf[2 * sp + 1][0] = t2; bf[2 * sp + 1][1] = t3;
                }
                float d0 = 0, d1 = 0, d2 = 0, d3 = 0;
#pragma unroll
                for (int s = 0; s < 8; s++)
                    mma16816(d0, d1, d2, d3, ahi[s][0], ahi[s][1], ahi[s][2], ahi[s][3],
                             bf[s][0], bf[s][1]);
                float y0 = d0 * __expf(d0), y1 = d1 * __expf(d1);
                float y2 = d2 * __expf(d2), y3 = d3 * __expf(d3);
                mA = fmaxf(mA, fmaxf(d0, d1));
                mB = fmaxf(mB, fmaxf(d2, d3));
                TA += fabsf(y0) + fabsf(y1);
                TB += fabsf(y2) + fabsf(y3);
                __half2 p0 = __floats2half2_rn(y0, y1);
                __half2 p1 = __floats2half2_rn(y2, y3);
                int qb = nt * 16 + 4 * c4;           // byte within 256B row
                *(uint32_t*)(yrA + ((qb + rotA) & 255)) = *(uint32_t*)&p0;
                *(uint32_t*)(yrB + ((qb + rotB) & 255)) = *(uint32_t*)&p1;
            }
        }
        __syncthreads();   // MMA done reading X(buf), y staged

        // prefetch qt+2 into the just-consumed buffer
        if (qt < 2) {
            const uint4* gqn = (const uint4*)(g_qh + (size_t)(b * 4 + qt + 2) * 32768);
            uint32_t xd = smb + (buf ? X1_OFF : X0_OFF);
            for (int i = tid; i < 2048; i += 256) cp16(xd + i * 16, gqn + i);
            CP_COMMIT();
        }
        // copy y staging -> g_xe
        for (int idx = tid; idx < 2048; idx += 256) {
            int uu = idx >> 4, c = idx & 15;
            uint4 v = *(const uint4*)(sm + A_OFF + uu * 256 + ((c * 16 + uu * 16) & 255));
            dst[uu * 64 + qt * 16 + c] = v;
        }
        if (qt < 3) {
            if (qt == 2) { CP_WAIT(0); } else { CP_WAIT(1); }
            __syncthreads();
        }
    }

    // reduce stats over the 4 lanes of each quad
    mA = fmaxf(mA, __shfl_xor_sync(0xFFFFFFFFu, mA, 1));
    mA = fmaxf(mA, __shfl_xor_sync(0xFFFFFFFFu, mA, 2));
    TA += __shfl_xor_sync(0xFFFFFFFFu, TA, 1);
    TA += __shfl_xor_sync(0xFFFFFFFFu, TA, 2);
    mB = fmaxf(mB, __shfl_xor_sync(0xFFFFFFFFu, mB, 1));
    mB = fmaxf(mB, __shfl_xor_sync(0xFFFFFFFFu, mB, 2));
    TB += __shfl_xor_sync(0xFFFFFFFFu, TB, 1);
    TB += __shfl_xor_sync(0xFFFFFFFFu, TB, 2);

    float* smm = (float*)(sm + STAT_OFF);
    float* smt = smm + 128;
    if (c4 == 0) {
        smm[u0 + r4] = mA;      smt[u0 + r4] = TA;
        smm[u0 + 8 + r4] = mB;  smt[u0 + 8 + r4] = TB;
    }
    __syncthreads();

    if (tid < 128) {
        float m = smm[tid], T = smt[tid];
        float vu = g_v[((size_t)b * KK + kidx) * TT + tid];
        g_w[((size_t)b * KK + kidx) * TT + tid] = vu / (T + __expf(m));
    }
}

// ---------------- pass 2: partial out over k-chunk of 32; 16 replicas ----------------
// grid: (32, BB*NREP) -> 8192 threads per (b,kc) slice: u in [0,128), qg in [0,64)
__global__ __launch_bounds__(256) void pass2() {
    int bykc = blockIdx.y;                       // b*16 + kc
    int b = bykc >> 4, kc = bykc & 15;
    int s = blockIdx.x * 256 + threadIdx.x;      // 8192 per slice
    int qg = s & 63, u = s >> 6;                 // u in [0,128)
    const uint4* src = (const uint4*)(g_xe + ((size_t)(b * KK + kc * 32) * TT + u) * QQ) + qg;
    const float* wp = g_w + ((size_t)b * KK + (size_t)kc * 32) * TT + u;
    const size_t kstride = (size_t)TT * QQ / 8;  // uint4 step per k
    float acc[8];
#pragma unroll
    for (int j = 0; j < 8; j++) acc[j] = 0.0f;
#pragma unroll 4
    for (int k = 0; k < 32; k++) {
        uint4 yv = src[(size_t)k * kstride];
        float wv = wp[(size_t)k * TT];
        float2 f0 = __half22float2(*(__half2*)&yv.x);
        float2 f1 = __half22float2(*(__half2*)&yv.y);
        float2 f2 = __half22float2(*(__half2*)&yv.z);
        float2 f3 = __half22float2(*(__half2*)&yv.w);
        acc[0] = fmaf(wv, f0.x, acc[0]); acc[1] = fmaf(wv, f0.y, acc[1]);
        acc[2] = fmaf(wv, f1.x, acc[2]); acc[3] = fmaf(wv, f1.y, acc[3]);
        acc[4] = fmaf(wv, f2.x, acc[4]); acc[5] = fmaf(wv, f2.y, acc[5]);
        acc[6] = fmaf(wv, f3.x, acc[6]); acc[7] = fmaf(wv, f3.y, acc[7]);
    }
    float* dstp = g_accr + (size_t)(bykc & 15) * BB * QQ * TT;
    int q0 = qg * 8;
#pragma unroll
    for (int j = 0; j < 8; j++)
        dstp[((size_t)b * QQ + q0 + j) * TT + u] = acc[j];
}

// ---------------- launch ----------------
extern "C" void kernel_launch(void* const* d_in, const int* in_sizes, int n_in,
                              void* d_out, int out_size) {
    const float* q_in = (const float*)d_in[0];
    const float* k_in = (const float*)d_in[1];
    const float* v_in = (const float*)d_in[2];
    const float* Wk   = (const float*)d_in[3];
    const float* Wq   = (const float*)d_in[4];
    const float* Wv   = (const float*)d_in[5];
    const float* Wl   = (const float*)d_in[6];
    const float* Wo   = (const float*)d_in[7];
    float* out = (float*)d_out;

    const int SMEM_G = (128 * 132 + 32 * 132) * 4;   // 84480
    cudaFuncSetAttribute(gemm_out, cudaFuncAttributeMaxDynamicSharedMemorySize, SMEM_G);
    cudaFuncSetAttribute(proj3,    cudaFuncAttributeMaxDynamicSharedMemorySize, SMEM_G);
    cudaFuncSetAttribute(pass1,    cudaFuncAttributeMaxDynamicSharedMemorySize, P1_SMEM);

    proj3<<<dim3(32, 3), 256, SMEM_G>>>(q_in, Wq, k_in, Wk, v_in, Wv);
    prep_images<<<BB * KK + 8, 256>>>(Wl);
    pass1<<<BB * KK, 256, P1_SMEM>>>();
    pass2<<<dim3(32, BB * NREP), 256>>>();
    gemm_out<<<32, 256, SMEM_G>>>(Wo, out);
}

// round 9
// speedup vs baseline: 4.3244x; 1.0729x over previous
#include <cuda_runtime.h>
#include <cuda_fp16.h>
#include <cstdint>

#define BB 2
#define KK 512
#define QQ 512
#define TT 128
#define NREP 16

// ---------------- device scratch ----------------
__device__ float g_k[BB * KK * TT];
__device__ float g_q[BB * QQ * TT];
__device__ float g_v[BB * KK * TT];
__device__ float g_w[BB * KK * TT];                  // per (b,k,u) scale v_u/(T+e^m)
__device__ float g_accr[NREP * BB * QQ * TT];        // k-split partial sums
__device__ __half g_xe[(size_t)BB * KK * TT * QQ];   // 128MB unscaled y = x*e^x
__device__ unsigned char g_ak[(size_t)BB * KK * 32768];  // 32MB swizzled fp16 Wl*k images
__device__ unsigned char g_qh[BB * 4 * 32768];           // 256KB swizzled fp16 q tiles

// ---------------- helpers ----------------
__device__ __forceinline__ uint32_t smem_u32(const void* p) {
    uint32_t a;
    asm("{ .reg .u64 t; cvta.to.shared.u64 t, %1; cvt.u32.u64 %0, t; }" : "=r"(a) : "l"(p));
    return a;
}
__device__ __forceinline__ void ldsm_x4(uint32_t& r0, uint32_t& r1, uint32_t& r2, uint32_t& r3,
                                        uint32_t addr) {
    asm volatile("ldmatrix.sync.aligned.m8n8.x4.shared.b16 {%0,%1,%2,%3}, [%4];"
                 : "=r"(r0), "=r"(r1), "=r"(r2), "=r"(r3) : "r"(addr));
}
__device__ __forceinline__ void mma16816(float& d0, float& d1, float& d2, float& d3,
                                         uint32_t a0, uint32_t a1, uint32_t a2, uint32_t a3,
                                         uint32_t b0, uint32_t b1) {
    asm volatile("mma.sync.aligned.m16n8k16.row.col.f32.f16.f16.f32 "
                 "{%0,%1,%2,%3}, {%4,%5,%6,%7}, {%8,%9}, {%0,%1,%2,%3};"
                 : "+f"(d0), "+f"(d1), "+f"(d2), "+f"(d3)
                 : "r"(a0), "r"(a1), "r"(a2), "r"(a3), "r"(b0), "r"(b1));
}
__device__ __forceinline__ void cp16(uint32_t smem, const void* g) {
    asm volatile("cp.async.cg.shared.global [%0], [%1], 16;" :: "r"(smem), "l"(g));
}
#define CP_COMMIT() asm volatile("cp.async.commit_group;" ::: "memory")
#define CP_WAIT(N)  asm volatile("cp.async.wait_group %0;" :: "n"(N) : "memory")

// smem byte layout for pass1 (total 99328 -> 2 CTAs/SM)
#define A_OFF    0          // 32KB: A_k image; reused as y staging after frag load
#define X0_OFF   32768      // 32KB X buffer 0
#define X1_OFF   65536      // 32KB X buffer 1
#define STAT_OFF 98304      // m[128], T[128] = 1KB
#define P1_SMEM  99328

// ---------------- prep: build swizzled fp16 images ----------------
__global__ __launch_bounds__(256) void prep_images(const float* __restrict__ Wl) {
    int blk = blockIdx.x;
    int tid = threadIdx.x;
    int r = tid >> 1, h = tid & 1;
    int r7 = r & 7;
    if (blk < BB * KK) {
        int b = blk >> 9, k = blk & 511;
        const float4* wrow = (const float4*)(Wl + (size_t)r * TT + h * 64);
        const float4* krow = (const float4*)(g_k + ((size_t)b * KK + k) * TT + h * 64);
        unsigned char* arow = g_ak + (size_t)blk * 32768 + r * 256;
#pragma unroll
        for (int c8 = 0; c8 < 8; c8++) {
            float4 qa = wrow[c8 * 2], qb = wrow[c8 * 2 + 1];
            float4 ka = krow[c8 * 2], kb = krow[c8 * 2 + 1];
            __half2 h0 = __floats2half2_rn(qa.x * ka.x, qa.y * ka.y);
            __half2 h1 = __floats2half2_rn(qa.z * ka.z, qa.w * ka.w);
            __half2 h2 = __floats2half2_rn(qb.x * kb.x, qb.y * kb.y);
            __half2 h3 = __floats2half2_rn(qb.z * kb.z, qb.w * kb.w);
            int chunk = h * 8 + c8;
            uint4 pk;
            pk.x = *(uint32_t*)&h0; pk.y = *(uint32_t*)&h1;
            pk.z = *(uint32_t*)&h2; pk.w = *(uint32_t*)&h3;
            *(uint4*)(arow + ((chunk ^ r7) << 4)) = pk;
        }
    } else {
        int i = blk - BB * KK;            // 0..7: b = i>>2, qt = i&3
        int b = i >> 2, qt = i & 3;
        const float4* qrow = (const float4*)(g_q + ((size_t)b * QQ + qt * 128 + r) * TT + h * 64);
        unsigned char* xrow = g_qh + (size_t)i * 32768 + r * 256;
#pragma unroll
        for (int c8 = 0; c8 < 8; c8++) {
            float4 qa = qrow[c8 * 2], qb = qrow[c8 * 2 + 1];
            __half2 h0 = __floats2half2_rn(qa.x, qa.y);
            __half2 h1 = __floats2half2_rn(qa.z, qa.w);
            __half2 h2 = __floats2half2_rn(qb.x, qb.y);
            __half2 h3 = __floats2half2_rn(qb.z, qb.w);
            int chunk = h * 8 + c8;
            uint4 pk;
            pk.x = *(uint32_t*)&h0; pk.y = *(uint32_t*)&h1;
            pk.z = *(uint32_t*)&h2; pk.w = *(uint32_t*)&h3;
            *(uint4*)(xrow + ((chunk ^ r7) << 4)) = pk;
        }
    }
}

// ---------------- fp32 GEMM 32-row tiles: out[r,u] = sum_t in[r,t]*W[u,t] ----------------
__device__ __forceinline__ void gemm32_body(const float* __restrict__ in,
                                            const float* __restrict__ W,
                                            float* __restrict__ out, int r0, int sumrep) {
    extern __shared__ float smf[];
    float* sW = smf;                 // [128][132]
    float* sI = smf + 128 * 132;     // [32][132]
    int tid = threadIdx.x;
    for (int i = tid; i < 128 * 128; i += 256) { int u = i >> 7, t = i & 127; sW[u * 132 + t] = W[i]; }
    for (int i = tid; i < 32 * 128;  i += 256) {
        int r = i >> 7, t = i & 127;
        float v;
        if (sumrep) {
            const size_t off = (size_t)r0 * 128 + i;
            const size_t st = (size_t)BB * QQ * TT;
            v = 0.0f;
#pragma unroll
            for (int rr = 0; rr < NREP; rr++) v += in[off + (size_t)rr * st];
        } else {
            v = in[(size_t)r0 * 128 + i];
        }
        sI[r * 132 + t] = v;
    }
    __syncthreads();
    int tx = tid & 15, ty = tid >> 4;
    float acc[2][8];
#pragma unroll
    for (int i = 0; i < 2; i++)
#pragma unroll
        for (int j = 0; j < 8; j++) acc[i][j] = 0.0f;
    for (int t = 0; t < 128; t += 4) {
        float4 a0 = *(const float4*)&sI[(ty * 2 + 0) * 132 + t];
        float4 a1 = *(const float4*)&sI[(ty * 2 + 1) * 132 + t];
#pragma unroll
        for (int j = 0; j < 8; j++) {
            float4 bv = *(const float4*)&sW[(tx + 16 * j) * 132 + t];
            acc[0][j] = fmaf(a0.x, bv.x, acc[0][j]); acc[0][j] = fmaf(a0.y, bv.y, acc[0][j]);
            acc[0][j] = fmaf(a0.z, bv.z, acc[0][j]); acc[0][j] = fmaf(a0.w, bv.w, acc[0][j]);
            acc[1][j] = fmaf(a1.x, bv.x, acc[1][j]); acc[1][j] = fmaf(a1.y, bv.y, acc[1][j]);
            acc[1][j] = fmaf(a1.z, bv.z, acc[1][j]); acc[1][j] = fmaf(a1.w, bv.w, acc[1][j]);
        }
    }
#pragma unroll
    for (int i = 0; i < 2; i++)
#pragma unroll
        for (int j = 0; j < 8; j++)
            out[(size_t)(r0 + ty * 2 + i) * 128 + tx + 16 * j] = acc[i][j];
}

__global__ __launch_bounds__(256) void gemm_out(const float* __restrict__ W,
                                                float* __restrict__ out) {
    gemm32_body(g_accr, W, out, blockIdx.x * 32, 1);
}

__global__ __launch_bounds__(256) void proj3(const float* __restrict__ qi, const float* __restrict__ Wq,
                                             const float* __restrict__ ki, const float* __restrict__ Wk,
                                             const float* __restrict__ vi, const float* __restrict__ Wv) {
    int r0 = blockIdx.x * 32;
    if (blockIdx.y == 0)      gemm32_body(qi, Wq, g_q, r0, 0);
    else if (blockIdx.y == 1) gemm32_body(ki, Wk, g_k, r0, 0);
    else                      gemm32_body(vi, Wv, g_v, r0, 0);
}

// load B-fragments for one nt row-block
#define LOAD_BF(dst, ntv)                                                      \
    do {                                                                       \
        int row_ = (ntv) * 8 + brow7;                                          \
        uint32_t rb_ = xb + row_ * 256;                                        \
        int r7_ = row_ & 7;                                                    \
        _Pragma("unroll")                                                      \
        for (int sp = 0; sp < 4; sp++) {                                       \
            int chunk_ = 4 * sp + bgrp;                                        \
            uint32_t t0_, t1_, t2_, t3_;                                       \
            ldsm_x4(t0_, t1_, t2_, t3_, rb_ + ((chunk_ ^ r7_) << 4));          \
            dst[2 * sp][0] = t0_; dst[2 * sp][1] = t1_;                        \
            dst[2 * sp + 1][0] = t2_; dst[2 * sp + 1][1] = t3_;                \
        }                                                                      \
    } while (0)

// ---------------- pass 1: CTA per (b,k) ----------------
__global__ __launch_bounds__(256, 2) void pass1() {
    extern __shared__ unsigned char sm[];
    int tid = threadIdx.x, wid = tid >> 5, lane = tid & 31;
    int b = blockIdx.x >> 9, kidx = blockIdx.x & 511;
    uint32_t smb = smem_u32(sm);

    {
        const uint4* gak = (const uint4*)(g_ak + (size_t)blockIdx.x * 32768);
        const uint4* gq0 = (const uint4*)(g_qh + (size_t)(b * 4 + 0) * 32768);
        const uint4* gq1 = (const uint4*)(g_qh + (size_t)(b * 4 + 1) * 32768);
        for (int i = tid; i < 2048; i += 256) {
            cp16(smb + A_OFF + i * 16, gak + i);
            cp16(smb + X0_OFF + i * 16, gq0 + i);
        }
        CP_COMMIT();
        for (int i = tid; i < 2048; i += 256) cp16(smb + X1_OFF + i * 16, gq1 + i);
        CP_COMMIT();
    }
    CP_WAIT(1);
    __syncthreads();

    // A fragments: warp wid owns u-rows [wid*16, +16), K=128 (8 k-steps)
    int u0 = wid * 16;
    uint32_t ahi[8][4];
    {
        int row = u0 + (lane & 7) + ((lane >> 3) & 1) * 8;
        int cpar = (lane >> 4) & 1;
        int r7 = lane & 7;
        uint32_t rbh = smb + A_OFF + row * 256;
#pragma unroll
        for (int s = 0; s < 8; s++) {
            int chunk = 2 * s + cpar;
            ldsm_x4(ahi[s][0], ahi[s][1], ahi[s][2], ahi[s][3], rbh + ((chunk ^ r7) << 4));
        }
    }
    __syncthreads();   // A region now free for y staging

    int r4 = lane >> 2, c4 = lane & 3;
    float mA = -1e30f, TA = 0.0f, mB = -1e30f, TB = 0.0f;
    uint4* dst = (uint4*)(g_xe + ((size_t)(b * KK + kidx) * TT) * QQ);

    for (int qt = 0; qt < 4; qt++) {
        int buf = qt & 1;
        uint32_t xb = smb + (buf ? X1_OFF : X0_OFF);
        // pipelined MMA + exp epilogue + inline flush to A region
        {
            int brow7 = lane & 7;
            int bgrp = lane >> 3;         // 0..3
            int uA = u0 + r4, uB = u0 + 8 + r4;
            unsigned char* yrA = sm + A_OFF + uA * 256;
            unsigned char* yrB = sm + A_OFF + uB * 256;
            int rotA = uA * 16, rotB = uB * 16;
            uint32_t bf0[8][2], bf1[8][2];
            LOAD_BF(bf0, 0);
#pragma unroll
            for (int nt = 0; nt < 16; nt++) {
                uint32_t (*cur)[2] = (nt & 1) ? bf1 : bf0;
                uint32_t (*nxt)[2] = (nt & 1) ? bf0 : bf1;
                float d0 = 0, d1 = 0, d2 = 0, d3 = 0;
#pragma unroll
                for (int s = 0; s < 8; s++)
                    mma16816(d0, d1, d2, d3, ahi[s][0], ahi[s][1], ahi[s][2], ahi[s][3],
                             cur[s][0], cur[s][1]);
                if (nt < 15) LOAD_BF(nxt, nt + 1);
                float y0 = d0 * __expf(d0), y1 = d1 * __expf(d1);
                float y2 = d2 * __expf(d2), y3 = d3 * __expf(d3);
                mA = fmaxf(mA, fmaxf(d0, d1));
                mB = fmaxf(mB, fmaxf(d2, d3));
                TA += fabsf(y0) + fabsf(y1);
                TB += fabsf(y2) + fabsf(y3);
                __half2 p0 = __floats2half2_rn(y0, y1);
                __half2 p1 = __floats2half2_rn(y2, y3);
                int qb = nt * 16 + 4 * c4;           // byte within 256B row
                *(uint32_t*)(yrA + ((qb + rotA) & 255)) = *(uint32_t*)&p0;
                *(uint32_t*)(yrB + ((qb + rotB) & 255)) = *(uint32_t*)&p1;
            }
        }
        __syncthreads();   // MMA done reading X(buf), y staged

        // prefetch qt+2 into the just-consumed buffer
        if (qt < 2) {
            const uint4* gqn = (const uint4*)(g_qh + (size_t)(b * 4 + qt + 2) * 32768);
            uint32_t xd = smb + (buf ? X1_OFF : X0_OFF);
            for (int i = tid; i < 2048; i += 256) cp16(xd + i * 16, gqn + i);
            CP_COMMIT();
        }
        // copy y staging -> g_xe (streaming stores)
        for (int idx = tid; idx < 2048; idx += 256) {
            int uu = idx >> 4, c = idx & 15;
            uint4 v = *(const uint4*)(sm + A_OFF + uu * 256 + ((c * 16 + uu * 16) & 255));
            __stcs(&dst[uu * 64 + qt * 16 + c], v);
        }
        if (qt < 3) {
            if (qt == 2) { CP_WAIT(0); } else { CP_WAIT(1); }
            __syncthreads();
        }
    }

    // reduce stats over the 4 lanes of each quad
    mA = fmaxf(mA, __shfl_xor_sync(0xFFFFFFFFu, mA, 1));
    mA = fmaxf(mA, __shfl_xor_sync(0xFFFFFFFFu, mA, 2));
    TA += __shfl_xor_sync(0xFFFFFFFFu, TA, 1);
    TA += __shfl_xor_sync(0xFFFFFFFFu, TA, 2);
    mB = fmaxf(mB, __shfl_xor_sync(0xFFFFFFFFu, mB, 1));
    mB = fmaxf(mB, __shfl_xor_sync(0xFFFFFFFFu, mB, 2));
    TB += __shfl_xor_sync(0xFFFFFFFFu, TB, 1);
    TB += __shfl_xor_sync(0xFFFFFFFFu, TB, 2);

    float* smm = (float*)(sm + STAT_OFF);
    float* smt = smm + 128;
    if (c4 == 0) {
        smm[u0 + r4] = mA;      smt[u0 + r4] = TA;
        smm[u0 + 8 + r4] = mB;  smt[u0 + 8 + r4] = TB;
    }
    __syncthreads();

    if (tid < 128) {
        float m = smm[tid], T = smt[tid];
        float vu = g_v[((size_t)b * KK + kidx) * TT + tid];
        g_w[((size_t)b * KK + kidx) * TT + tid] = vu / (T + __expf(m));
    }
}

// ---------------- pass 2: partial out over k-chunk of 32; 16 replicas ----------------
// grid: (32, BB*NREP) -> 8192 threads per (b,kc) slice: u in [0,128), qg in [0,64)
__global__ __launch_bounds__(256) void pass2() {
    __shared__ float ws[32 * 4];                 // w[k][u_local] for this CTA
    int bykc = blockIdx.y;                       // b*16 + kc
    int b = bykc >> 4, kc = bykc & 15;
    int s = blockIdx.x * 256 + threadIdx.x;      // 8192 per slice
    int qg = s & 63, u = s >> 6;                 // u in [0,128)
    int ubase = (blockIdx.x * 256) >> 6;         // 4 u values per CTA
    if (threadIdx.x < 128) {
        int kk = threadIdx.x >> 2, ul = threadIdx.x & 3;
        ws[kk * 4 + ul] = g_w[((size_t)b * KK + kc * 32 + kk) * TT + ubase + ul];
    }
    __syncthreads();
    int ul = u - ubase;
    const uint4* src = (const uint4*)(g_xe + ((size_t)(b * KK + kc * 32) * TT + u) * QQ) + qg;
    const size_t kstride = (size_t)TT * QQ / 8;  // uint4 step per k
    float acc[8];
#pragma unroll
    for (int j = 0; j < 8; j++) acc[j] = 0.0f;
#pragma unroll 8
    for (int k = 0; k < 32; k++) {
        uint4 yv = __ldcs(&src[(size_t)k * kstride]);
        float wv = ws[k * 4 + ul];
        float2 f0 = __half22float2(*(__half2*)&yv.x);
        float2 f1 = __half22float2(*(__half2*)&yv.y);
        float2 f2 = __half22float2(*(__half2*)&yv.z);
        float2 f3 = __half22float2(*(__half2*)&yv.w);
        acc[0] = fmaf(wv, f0.x, acc[0]); acc[1] = fmaf(wv, f0.y, acc[1]);
        acc[2] = fmaf(wv, f1.x, acc[2]); acc[3] = fmaf(wv, f1.y, acc[3]);
        acc[4] = fmaf(wv, f2.x, acc[4]); acc[5] = fmaf(wv, f2.y, acc[5]);
        acc[6] = fmaf(wv, f3.x, acc[6]); acc[7] = fmaf(wv, f3.y, acc[7]);
    }
    float* dstp = g_accr + (size_t)kc * BB * QQ * TT;
    int q0 = qg * 8;
#pragma unroll
    for (int j = 0; j < 8; j++)
        dstp[((size_t)b * QQ + q0 + j) * TT + u] = acc[j];
}

// ---------------- launch ----------------
extern "C" void kernel_launch(void* const* d_in, const int* in_sizes, int n_in,
                              void* d_out, int out_size) {
    const float* q_in = (const float*)d_in[0];
    const float* k_in = (const float*)d_in[1];
    const float* v_in = (const float*)d_in[2];
    const float* Wk   = (const float*)d_in[3];
    const float* Wq   = (const float*)d_in[4];
    const float* Wv   = (const float*)d_in[5];
    const float* Wl   = (const float*)d_in[6];
    const float* Wo   = (const float*)d_in[7];
    float* out = (float*)d_out;

    const int SMEM_G = (128 * 132 + 32 * 132) * 4;   // 84480
    cudaFuncSetAttribute(gemm_out, cudaFuncAttributeMaxDynamicSharedMemorySize, SMEM_G);
    cudaFuncSetAttribute(proj3,    cudaFuncAttributeMaxDynamicSharedMemorySize, SMEM_G);
    cudaFuncSetAttribute(pass1,    cudaFuncAttributeMaxDynamicSharedMemorySize, P1_SMEM);

    proj3<<<dim3(32, 3), 256, SMEM_G>>>(q_in, Wq, k_in, Wk, v_in, Wv);
    prep_images<<<BB * KK + 8, 256>>>(Wl);
    pass1<<<BB * KK, 256, P1_SMEM>>>();
    pass2<<<dim3(32, BB * NREP), 256>>>();
    gemm_out<<<32, 256, SMEM_G>>>(Wo, out);
}